// round 3
// baseline (speedup 1.0000x reference)
#include <cuda_runtime.h>

// Problem constants
#define NB 16       // batch
#define NC 256      // channels (DIM)
#define NS 4096     // spatial n = 64*64
#define NH 512      // hidden = heads*dim_head
#define NHEADS 8
#define NSPLIT 8
#define KCHUNK (NS / NSPLIT)   // 512

typedef unsigned long long u64;

// ---------------- scratch (static device memory; no allocations) -------------
__device__ float g_Gpart[NSPLIT][NB][NC][NC];  // 32 MB split-K partials
__device__ float g_G[NB][NC][NC];              // 4 MB  Gram matrices
__device__ float g_QG[NB][NH][NC];             // 8 MB  Wq * G
__device__ float g_M[NB][NH][NC];              // 8 MB  attn * Wv
__device__ float g_P[NB][NC][NC];              // 4 MB  W_out * M

// ---------------- packed fp32x2 helpers (Blackwell FFMA2) --------------------
__device__ __forceinline__ u64 pack2_dup(float v) {
    u64 r;
    asm("mov.b64 %0, {%1, %1};" : "=l"(r) : "f"(v));
    return r;
}
__device__ __forceinline__ void fma2(u64& d, u64 a, u64 b) {
    asm("fma.rn.f32x2 %0, %1, %2, %0;" : "+l"(d) : "l"(a), "l"(b));
}
__device__ __forceinline__ void unpack2(float& lo, float& hi, u64 v) {
    asm("mov.b64 {%0, %1}, %2;" : "=f"(lo), "=f"(hi) : "l"(v));
}

// =============================================================================
// Kernel 1: Gram partials.  Gpart[s][b] = X[b][:, ks] * X[b][:, ks]^T
// 128x128 tile per CTA, 256 threads, 8x8 micro-tile (packed as 8x4 f32x2).
// grid = (4 tiles, NSPLIT, NB)
// =============================================================================
__global__ __launch_bounds__(256) void gram_kernel(const float* __restrict__ x) {
    const int bi = blockIdx.x >> 1, bj = blockIdx.x & 1;
    const int s = blockIdx.y, b = blockIdx.z;
    const float* Xb = x + (size_t)b * NC * NS;

    __shared__ __align__(16) float As[16][132];
    __shared__ __align__(16) float Bs[16][132];

    const int tid = threadIdx.x, tx = tid & 15, ty = tid >> 4;
    u64 acc[8][4];
    const u64 z = 0ull;
#pragma unroll
    for (int i = 0; i < 8; i++)
#pragma unroll
        for (int jp = 0; jp < 4; jp++) acc[i][jp] = z;

    const int k0 = s * KCHUNK;
    for (int kt = k0; kt < k0 + KCHUNK; kt += 16) {
#pragma unroll
        for (int it = 0; it < 2; it++) {
            int idx = it * 256 + tid;
            int row = idx >> 2, k4 = idx & 3;
            float4 v = *(const float4*)(Xb + (size_t)(bi * 128 + row) * NS + kt + k4 * 4);
            As[k4 * 4 + 0][row] = v.x; As[k4 * 4 + 1][row] = v.y;
            As[k4 * 4 + 2][row] = v.z; As[k4 * 4 + 3][row] = v.w;
            float4 u = *(const float4*)(Xb + (size_t)(bj * 128 + row) * NS + kt + k4 * 4);
            Bs[k4 * 4 + 0][row] = u.x; Bs[k4 * 4 + 1][row] = u.y;
            Bs[k4 * 4 + 2][row] = u.z; Bs[k4 * 4 + 3][row] = u.w;
        }
        __syncthreads();
#pragma unroll
        for (int kk = 0; kk < 16; kk++) {
            u64 aP[8], bP[4];
#pragma unroll
            for (int i = 0; i < 8; i++) aP[i] = pack2_dup(As[kk][ty + 16 * i]);
#pragma unroll
            for (int jp = 0; jp < 4; jp++)
                bP[jp] = *(const u64*)(&Bs[kk][tx * 2 + 32 * jp]);
#pragma unroll
            for (int i = 0; i < 8; i++)
#pragma unroll
                for (int jp = 0; jp < 4; jp++) fma2(acc[i][jp], aP[i], bP[jp]);
        }
        __syncthreads();
    }

    float* Gp = &g_Gpart[s][b][0][0];
#pragma unroll
    for (int i = 0; i < 8; i++) {
        int r = bi * 128 + ty + 16 * i;
#pragma unroll
        for (int jp = 0; jp < 4; jp++) {
            float lo, hi;
            unpack2(lo, hi, acc[i][jp]);
            float2 o; o.x = lo; o.y = hi;
            *(float2*)&Gp[(size_t)r * NC + bj * 128 + tx * 2 + 32 * jp] = o;
        }
    }
}

// =============================================================================
// Kernel 2: deterministic split-K reduction.  G = sum_s Gpart[s]
// =============================================================================
__global__ __launch_bounds__(256) void reduce_g_kernel() {
    int i = blockIdx.x * blockDim.x + threadIdx.x;   // float4 index, 262144 total
    const float4* p = (const float4*)g_Gpart;
    const int stride = NB * NC * NC / 4;
    float4 sum = make_float4(0.f, 0.f, 0.f, 0.f);
#pragma unroll
    for (int s = 0; s < NSPLIT; s++) {
        float4 v = p[(size_t)s * stride + i];
        sum.x += v.x; sum.y += v.y; sum.z += v.z; sum.w += v.w;
    }
    ((float4*)g_G)[i] = sum;
}

// =============================================================================
// Kernel 3/5: batched 64x64-tile SGEMM.
// MODE 0: QG[b] = Wq(=w_qkv rows 0..511) * G[b]      (K=256), grid (4,8,NB)
// MODE 1: P[b]  = W_out * M[b]                       (K=512), grid (4,4,NB)
// =============================================================================
template <int MODE>
__global__ __launch_bounds__(256) void gemm64_kernel(const float* __restrict__ W) {
    const int nt = blockIdx.x, mt = blockIdx.y, b = blockIdx.z;
    const int K = (MODE == 0) ? 256 : 512;
    const int N = 256;
    const float* Ab = W;
    const float* Bb = (MODE == 0) ? &g_G[b][0][0] : &g_M[b][0][0];
    float* Cb = (MODE == 0) ? &g_QG[b][0][0] : &g_P[b][0][0];

    __shared__ __align__(16) float As[16][65];
    __shared__ __align__(16) float Bs[16][68];
    const int tid = threadIdx.x, tx = tid & 15, ty = tid >> 4;
    float acc[4][4] = {};

    for (int kt = 0; kt < K; kt += 16) {
        {
            int row = tid >> 2, k4 = tid & 3;
            float4 v = *(const float4*)(Ab + (size_t)(mt * 64 + row) * K + kt + k4 * 4);
            As[k4 * 4 + 0][row] = v.x; As[k4 * 4 + 1][row] = v.y;
            As[k4 * 4 + 2][row] = v.z; As[k4 * 4 + 3][row] = v.w;
            int kb = tid >> 4, n4 = tid & 15;
            *(float4*)&Bs[kb][n4 * 4] =
                *(const float4*)(Bb + (size_t)(kt + kb) * N + nt * 64 + n4 * 4);
        }
        __syncthreads();
#pragma unroll
        for (int kk = 0; kk < 16; kk++) {
            float a[4], bb[4];
#pragma unroll
            for (int i = 0; i < 4; i++) a[i] = As[kk][ty + 16 * i];
#pragma unroll
            for (int j = 0; j < 4; j++) bb[j] = Bs[kk][tx + 16 * j];
#pragma unroll
            for (int i = 0; i < 4; i++)
#pragma unroll
                for (int j = 0; j < 4; j++) acc[i][j] += a[i] * bb[j];
        }
        __syncthreads();
    }
#pragma unroll
    for (int i = 0; i < 4; i++)
#pragma unroll
        for (int j = 0; j < 4; j++)
            Cb[(size_t)(mt * 64 + ty + 16 * i) * N + nt * 64 + tx + 16 * j] = acc[i][j];
}

// =============================================================================
// Kernel 4: per-(batch,head) attention core.
//   sim = scale * QG_h * Wk_h^T  (64x64, K=256)  -> softmax rows
//   M_h = attn * Wv_h            (64x256)
// grid = (NHEADS, NB), 256 threads
// =============================================================================
__global__ __launch_bounds__(256) void attn_kernel(const float* __restrict__ wqkv) {
    const int h = blockIdx.x, b = blockIdx.y;
    __shared__ float S[64][65];
    __shared__ __align__(16) float Buf[4160];
    const int tid = threadIdx.x, tx = tid & 15, ty = tid >> 4;

    const float* QGb = &g_QG[b][h * 64][0];
    const float* Wk = wqkv + (size_t)(NH + h * 64) * NC;
    const float* Wv = wqkv + (size_t)(2 * NH + h * 64) * NC;
    float* Qs = Buf;            // [64][32]
    float* Ks = Buf + 64 * 32;  // [32][65] (transposed, padded)

    float acc[4][4] = {};
    for (int kc = 0; kc < NC; kc += 32) {
#pragma unroll
        for (int it = 0; it < 2; it++) {
            int idx = it * 256 + tid;
            int row = idx >> 3, c4 = idx & 7;
            *(float4*)&Qs[row * 32 + c4 * 4] =
                *(const float4*)(QGb + (size_t)row * NC + kc + c4 * 4);
            float4 v = *(const float4*)(Wk + (size_t)row * NC + kc + c4 * 4);
            Ks[(c4 * 4 + 0) * 65 + row] = v.x;
            Ks[(c4 * 4 + 1) * 65 + row] = v.y;
            Ks[(c4 * 4 + 2) * 65 + row] = v.z;
            Ks[(c4 * 4 + 3) * 65 + row] = v.w;
        }
        __syncthreads();
#pragma unroll
        for (int kk = 0; kk < 32; kk++) {
            float a[4], bb[4];
#pragma unroll
            for (int i = 0; i < 4; i++) a[i] = Qs[(ty + 16 * i) * 32 + kk];
#pragma unroll
            for (int j = 0; j < 4; j++) bb[j] = Ks[kk * 65 + tx + 16 * j];
#pragma unroll
            for (int i = 0; i < 4; i++)
#pragma unroll
                for (int j = 0; j < 4; j++) acc[i][j] += a[i] * bb[j];
        }
        __syncthreads();
    }
    const float scale = 0.125f;  // 64^-0.5
#pragma unroll
    for (int i = 0; i < 4; i++)
#pragma unroll
        for (int j = 0; j < 4; j++)
            S[ty + 16 * i][tx + 16 * j] = acc[i][j] * scale;
    __syncthreads();

    if (tid < 64) {
        float m = -1e30f;
        for (int j = 0; j < 64; j++) m = fmaxf(m, S[tid][j]);
        float sum = 0.f;
        for (int j = 0; j < 64; j++) {
            float e = expf(S[tid][j] - m);
            S[tid][j] = e;
            sum += e;
        }
        float inv = 1.f / sum;
        for (int j = 0; j < 64; j++) S[tid][j] *= inv;
    }
    __syncthreads();

    float* Ms = &g_M[b][h * 64][0];
    float* Vs = Buf;  // [64][64]
    for (int cc = 0; cc < NC; cc += 64) {
#pragma unroll
        for (int it = 0; it < 4; it++) {
            int idx = it * 256 + tid;
            int row = idx >> 4, c4 = idx & 15;
            *(float4*)&Vs[row * 64 + c4 * 4] =
                *(const float4*)(Wv + (size_t)row * NC + cc + c4 * 4);
        }
        __syncthreads();
        float o[4][4] = {};
        for (int j = 0; j < 64; j++) {
            float a[4], vv[4];
#pragma unroll
            for (int i = 0; i < 4; i++) a[i] = S[ty + 16 * i][j];
#pragma unroll
            for (int jj = 0; jj < 4; jj++) vv[jj] = Vs[j * 64 + tx + 16 * jj];
#pragma unroll
            for (int i = 0; i < 4; i++)
#pragma unroll
                for (int jj = 0; jj < 4; jj++) o[i][jj] += a[i] * vv[jj];
        }
#pragma unroll
        for (int i = 0; i < 4; i++)
#pragma unroll
            for (int jj = 0; jj < 4; jj++)
                Ms[(size_t)(ty + 16 * i) * NC + cc + tx + 16 * jj] = o[i][jj];
        __syncthreads();
    }
}

// =============================================================================
// Kernel 6: final = P[b] * X[b] + bias  -> d_out.  128x128 tiles, f32x2 inner.
// grid = (32, 2, NB)
// =============================================================================
__global__ __launch_bounds__(256) void final_kernel(const float* __restrict__ x,
                                                    const float* __restrict__ bias,
                                                    float* __restrict__ out) {
    const int nt = blockIdx.x, mt = blockIdx.y, b = blockIdx.z;
    const float* Pb = &g_P[b][0][0];
    const float* Xb = x + (size_t)b * NC * NS;

    __shared__ __align__(16) float As[16][132];
    __shared__ __align__(16) float Bs[16][132];
    const int tid = threadIdx.x, tx = tid & 15, ty = tid >> 4;

    u64 acc[8][4];
#pragma unroll
    for (int i = 0; i < 8; i++)
#pragma unroll
        for (int jp = 0; jp < 4; jp++) acc[i][jp] = 0ull;

    for (int kt = 0; kt < NC; kt += 16) {
#pragma unroll
        for (int it = 0; it < 2; it++) {
            int idx = it * 256 + tid;
            int row = idx >> 2, k4 = idx & 3;
            float4 v = *(const float4*)(Pb + (size_t)(mt * 128 + row) * NC + kt + k4 * 4);
            As[k4 * 4 + 0][row] = v.x; As[k4 * 4 + 1][row] = v.y;
            As[k4 * 4 + 2][row] = v.z; As[k4 * 4 + 3][row] = v.w;
            int k = idx >> 5, n4 = idx & 31;
            *(float4*)&Bs[k][n4 * 4] =
                *(const float4*)(Xb + (size_t)(kt + k) * NS + nt * 128 + n4 * 4);
        }
        __syncthreads();
#pragma unroll
        for (int kk = 0; kk < 16; kk++) {
            u64 aP[8], bP[4];
#pragma unroll
            for (int i = 0; i < 8; i++) aP[i] = pack2_dup(As[kk][ty + 16 * i]);
#pragma unroll
            for (int jp = 0; jp < 4; jp++)
                bP[jp] = *(const u64*)(&Bs[kk][tx * 2 + 32 * jp]);
#pragma unroll
            for (int i = 0; i < 8; i++)
#pragma unroll
                for (int jp = 0; jp < 4; jp++) fma2(acc[i][jp], aP[i], bP[jp]);
        }
        __syncthreads();
    }

#pragma unroll
    for (int i = 0; i < 8; i++) {
        int o = mt * 128 + ty + 16 * i;
        float bv = bias[o];
#pragma unroll
        for (int jp = 0; jp < 4; jp++) {
            float lo, hi;
            unpack2(lo, hi, acc[i][jp]);
            float2 w; w.x = lo + bv; w.y = hi + bv;
            *(float2*)&out[((size_t)b * NC + o) * NS + nt * 128 + tx * 2 + 32 * jp] = w;
        }
    }
}

// =============================================================================
extern "C" void kernel_launch(void* const* d_in, const int* in_sizes, int n_in,
                              void* d_out, int out_size) {
    (void)in_sizes; (void)n_in; (void)out_size;
    const float* x     = (const float*)d_in[0];  // [16,256,64,64]
    const float* w_qkv = (const float*)d_in[1];  // [1536,256]
    const float* w_out = (const float*)d_in[2];  // [256,512]
    const float* b_out = (const float*)d_in[3];  // [256]
    float* out = (float*)d_out;                  // [16,256,64,64]

    gram_kernel<<<dim3(4, NSPLIT, NB), 256>>>(x);
    reduce_g_kernel<<<NB * NC * NC / 4 / 256, 256>>>();
    gemm64_kernel<0><<<dim3(4, 8, NB), 256>>>(w_qkv);
    attn_kernel<<<dim3(NHEADS, NB), 256>>>(w_qkv);
    gemm64_kernel<1><<<dim3(4, 4, NB), 256>>>(w_out);
    final_kernel<<<dim3(32, 2, NB), 256>>>(x, b_out, out);
}

// round 9
// speedup vs baseline: 1.5222x; 1.5222x over previous
#include <cuda_runtime.h>
#include <cuda_bf16.h>

#define NB 16
#define NC 256
#define NS 4096
#define NH 512
#define NHEADS 8

typedef unsigned long long u64;
typedef unsigned int u32;
typedef unsigned short u16;

// ---------------- scratch (static device memory, 16B-aligned) ----------------
__device__ __align__(16) float g_Gpart[2][NB][NC][NC];       // 8 MB
__device__ __align__(16) float g_G[NB][NC][NC];              // 4 MB
__device__ __align__(16) float g_QG[NB][NH][NC];             // 8 MB
__device__ __align__(16) float g_M[NB][NH][NC];              // 8 MB
__device__ __align__(16) float g_P[NB][NC][NC];              // 4 MB
__device__ __align__(16) __nv_bfloat16 g_XThi[NB][NS][NC];   // 32 MB
__device__ __align__(16) __nv_bfloat16 g_XTlo[NB][NS][NC];   // 32 MB

// ---------------- helpers ----------------------------------------------------
__device__ __forceinline__ u32 smem_u32(const void* p) {
    u32 a;
    asm("{ .reg .u64 t; cvta.to.shared.u64 t, %1; cvt.u32.u64 %0, t; }" : "=r"(a) : "l"(p));
    return a;
}
__device__ __forceinline__ u64 pack2_dup(float v) {
    u64 r; asm("mov.b64 %0, {%1, %1};" : "=l"(r) : "f"(v)); return r;
}
__device__ __forceinline__ void fma2(u64& d, u64 a, u64 b) {
    asm("fma.rn.f32x2 %0, %1, %2, %0;" : "+l"(d) : "l"(a), "l"(b));
}
__device__ __forceinline__ void unpack2(float& lo, float& hi, u64 v) {
    asm("mov.b64 {%0, %1}, %2;" : "=f"(lo), "=f"(hi) : "l"(v));
}
// split fp32x4 -> 4 bf16 hi (packed u64) + 4 bf16 lo (packed u64)
__device__ __forceinline__ void split4(float4 v, u64& hv, u64& lv) {
    __nv_bfloat16 h0 = __float2bfloat16(v.x), h1 = __float2bfloat16(v.y);
    __nv_bfloat16 h2 = __float2bfloat16(v.z), h3 = __float2bfloat16(v.w);
    __nv_bfloat16 l0 = __float2bfloat16(v.x - __bfloat162float(h0));
    __nv_bfloat16 l1 = __float2bfloat16(v.y - __bfloat162float(h1));
    __nv_bfloat16 l2 = __float2bfloat16(v.z - __bfloat162float(h2));
    __nv_bfloat16 l3 = __float2bfloat16(v.w - __bfloat162float(h3));
    hv = (u64)__bfloat16_as_ushort(h0) | ((u64)__bfloat16_as_ushort(h1) << 16) |
         ((u64)__bfloat16_as_ushort(h2) << 32) | ((u64)__bfloat16_as_ushort(h3) << 48);
    lv = (u64)__bfloat16_as_ushort(l0) | ((u64)__bfloat16_as_ushort(l1) << 16) |
         ((u64)__bfloat16_as_ushort(l2) << 32) | ((u64)__bfloat16_as_ushort(l3) << 48);
}
__device__ __forceinline__ void ldsm4(u32* r, u32 addr) {
    asm volatile("ldmatrix.sync.aligned.m8n8.x4.shared.b16 {%0,%1,%2,%3}, [%4];"
                 : "=r"(r[0]), "=r"(r[1]), "=r"(r[2]), "=r"(r[3]) : "r"(addr));
}
__device__ __forceinline__ void mma_bf16(float* d, const u32* a, const u32* b) {
    asm volatile("mma.sync.aligned.m16n8k16.row.col.f32.bf16.bf16.f32 "
        "{%0,%1,%2,%3}, {%4,%5,%6,%7}, {%8,%9}, {%0,%1,%2,%3};"
        : "+f"(d[0]), "+f"(d[1]), "+f"(d[2]), "+f"(d[3])
        : "r"(a[0]), "r"(a[1]), "r"(a[2]), "r"(a[3]), "r"(b[0]), "r"(b[1]));
}

#define LDW 72                       // bf16 elems per smem row (64 + 8 pad; 144 B = 9*16)
#define TILE_E (128 * LDW)           // 9216 elems
#define MM_SMEM (4 * TILE_E * 2)     // 73728 bytes

// =============================================================================
// gram_mma: Gpart[s][b][bi*128..][bj*128..] = Xstrip_bi * Xstrip_bj^T
// over K half s (2048). 3-term bf16 split. grid (4,2,NB), 256 threads.
// =============================================================================
__global__ __launch_bounds__(256) void gram_mma(const float* __restrict__ x) {
    extern __shared__ __align__(16) __nv_bfloat16 sm[];
    __nv_bfloat16* Ah = sm;
    __nv_bfloat16* Al = sm + TILE_E;
    __nv_bfloat16* Bh = sm + 2 * TILE_E;
    __nv_bfloat16* Bl = sm + 3 * TILE_E;

    const int bi = blockIdx.x >> 1, bj = blockIdx.x & 1;
    const int s = blockIdx.y, b = blockIdx.z;
    const int tid = threadIdx.x, lane = tid & 31, wid = tid >> 5;
    const int wm = wid >> 2, wn = wid & 3;       // 2 x 4 warp grid, 64x32 tiles
    const float* Xb = x + (size_t)b * NC * NS;

    const u32 aHb = smem_u32(Ah), aLb = smem_u32(Al);
    const u32 bHb = smem_u32(Bh), bLb = smem_u32(Bl);
    const int g = lane >> 3, r8 = lane & 7;
    const int offA = (r8 + (g & 1) * 8) * LDW + (g >> 1) * 8;   // A ldmatrix lane offset
    const int offB = (r8 + (g >> 1) * 8) * LDW + (g & 1) * 8;   // B ldmatrix lane offset

    float acc[4][4][4] = {};   // [mfrag][nblk][reg]

    const int r0 = tid >> 4, kc4 = tid & 15;
    for (int c = 0; c < 32; c++) {               // 32 chunks of k=64
        const int k0 = s * 2048 + c * 64;
#pragma unroll
        for (int i = 0; i < 8; i++) {
            int row = r0 + 16 * i;
            float4 va = *(const float4*)(Xb + (size_t)(bi * 128 + row) * NS + k0 + kc4 * 4);
            u64 hv, lv; split4(va, hv, lv);
            *(u64*)&Ah[row * LDW + kc4 * 4] = hv;
            *(u64*)&Al[row * LDW + kc4 * 4] = lv;
            float4 vb = *(const float4*)(Xb + (size_t)(bj * 128 + row) * NS + k0 + kc4 * 4);
            split4(vb, hv, lv);
            *(u64*)&Bh[row * LDW + kc4 * 4] = hv;
            *(u64*)&Bl[row * LDW + kc4 * 4] = lv;
        }
        __syncthreads();
#pragma unroll
        for (int ks = 0; ks < 4; ks++) {
            u32 ah[4][4], al[4][4], bh[2][4], bl[2][4];
#pragma unroll
            for (int mf = 0; mf < 4; mf++) {
                u32 o = 2u * (u32)(offA + (wm * 64 + mf * 16) * LDW + ks * 16);
                ldsm4(ah[mf], aHb + o);
                ldsm4(al[mf], aLb + o);
            }
#pragma unroll
            for (int p = 0; p < 2; p++) {
                u32 o = 2u * (u32)(offB + (wn * 32 + p * 16) * LDW + ks * 16);
                ldsm4(bh[p], bHb + o);
                ldsm4(bl[p], bLb + o);
            }
#pragma unroll
            for (int mf = 0; mf < 4; mf++)
#pragma unroll
                for (int p = 0; p < 2; p++)
#pragma unroll
                    for (int hh = 0; hh < 2; hh++) {
                        int nb = p * 2 + hh;
                        mma_bf16(acc[mf][nb], ah[mf], &bh[p][hh * 2]);
                        mma_bf16(acc[mf][nb], ah[mf], &bl[p][hh * 2]);
                        mma_bf16(acc[mf][nb], al[mf], &bh[p][hh * 2]);
                    }
        }
        __syncthreads();
    }

    float* Gp = &g_Gpart[s][b][0][0];
    const int re = bi * 128 + wm * 64 + (lane >> 2);
    const int ce = bj * 128 + wn * 32 + 2 * (lane & 3);
#pragma unroll
    for (int mf = 0; mf < 4; mf++)
#pragma unroll
        for (int nb = 0; nb < 4; nb++) {
            int rr = re + mf * 16, cc = ce + nb * 8;
            float2 v0; v0.x = acc[mf][nb][0]; v0.y = acc[mf][nb][1];
            float2 v1; v1.x = acc[mf][nb][2]; v1.y = acc[mf][nb][3];
            *(float2*)&Gp[(size_t)rr * NC + cc] = v0;
            *(float2*)&Gp[(size_t)(rr + 8) * NC + cc] = v1;
        }
}

// =============================================================================
// convert_xt: X[b][c][ns] fp32 -> XT hi/lo [b][ns][c] bf16. grid (64,4,NB), 256t
// T padded to 68 cols (272 B row stride = 17*16) so float4 smem ops stay aligned.
// Packing done in u32 registers -> make_uint4 (no local-array casts).
// =============================================================================
__global__ __launch_bounds__(256) void convert_xt(const float* __restrict__ x) {
    __shared__ __align__(16) float T[64][68];
    const int ns0 = blockIdx.x * 64, c0 = blockIdx.y * 64, b = blockIdx.z;
    const int tid = threadIdx.x;
    {
        int r = tid >> 2, j = tid & 3;
        const float* src = x + ((size_t)b * NC + c0 + r) * NS + ns0 + j * 16;
        *(float4*)&T[r][j * 16 + 0] = *(const float4*)(src + 0);
        *(float4*)&T[r][j * 16 + 4] = *(const float4*)(src + 4);
        *(float4*)&T[r][j * 16 + 8] = *(const float4*)(src + 8);
        *(float4*)&T[r][j * 16 + 12] = *(const float4*)(src + 12);
    }
    __syncthreads();
    {
        int rn = tid >> 2, j = tid & 3;
        u32 hw[8], lw[8];
#pragma unroll
        for (int kk = 0; kk < 8; kk++) {
            float v0 = T[j * 16 + 2 * kk][rn];
            float v1 = T[j * 16 + 2 * kk + 1][rn];
            __nv_bfloat16 h0 = __float2bfloat16(v0), h1 = __float2bfloat16(v1);
            __nv_bfloat16 l0 = __float2bfloat16(v0 - __bfloat162float(h0));
            __nv_bfloat16 l1 = __float2bfloat16(v1 - __bfloat162float(h1));
            hw[kk] = (u32)__bfloat16_as_ushort(h0) | ((u32)__bfloat16_as_ushort(h1) << 16);
            lw[kk] = (u32)__bfloat16_as_ushort(l0) | ((u32)__bfloat16_as_ushort(l1) << 16);
        }
        uint4* dh = (uint4*)&g_XThi[b][ns0 + rn][c0 + j * 16];
        uint4* dl = (uint4*)&g_XTlo[b][ns0 + rn][c0 + j * 16];
        dh[0] = make_uint4(hw[0], hw[1], hw[2], hw[3]);
        dh[1] = make_uint4(hw[4], hw[5], hw[6], hw[7]);
        dl[0] = make_uint4(lw[0], lw[1], lw[2], lw[3]);
        dl[1] = make_uint4(lw[4], lw[5], lw[6], lw[7]);
    }
}

// =============================================================================
// reduce: G = Gpart[0] + Gpart[1]
// =============================================================================
__global__ __launch_bounds__(256) void reduce_g_kernel() {
    int i = blockIdx.x * 256 + threadIdx.x;
    const float4* p = (const float4*)g_Gpart;
    const int stride = NB * NC * NC / 4;
    float4 a = p[i], c = p[stride + i];
    a.x += c.x; a.y += c.y; a.z += c.z; a.w += c.w;
    ((float4*)g_G)[i] = a;
}

// =============================================================================
// gemm64 with FFMA2. MODE0: QG = Wq*G (K=256). MODE1: P = W_out*M (K=512)
// =============================================================================
template <int MODE>
__global__ __launch_bounds__(256) void gemm64_kernel(const float* __restrict__ W) {
    const int nt = blockIdx.x, mt = blockIdx.y, b = blockIdx.z;
    const int K = (MODE == 0) ? 256 : 512;
    const int N = 256;
    const float* Ab = W;
    const float* Bb = (MODE == 0) ? &g_G[b][0][0] : &g_M[b][0][0];
    float* Cb = (MODE == 0) ? &g_QG[b][0][0] : &g_P[b][0][0];

    __shared__ __align__(16) float As[16][65];
    __shared__ __align__(16) float Bs[16][68];
    const int tid = threadIdx.x, tx = tid & 15, ty = tid >> 4;
    u64 acc[4][2] = {};

    for (int kt = 0; kt < K; kt += 16) {
        {
            int row = tid >> 2, k4 = tid & 3;
            float4 v = *(const float4*)(Ab + (size_t)(mt * 64 + row) * K + kt + k4 * 4);
            As[k4 * 4 + 0][row] = v.x; As[k4 * 4 + 1][row] = v.y;
            As[k4 * 4 + 2][row] = v.z; As[k4 * 4 + 3][row] = v.w;
            int kb = tid >> 4, n4 = tid & 15;
            *(float4*)&Bs[kb][n4 * 4] = *(const float4*)(Bb + (size_t)(kt + kb) * N + nt * 64 + n4 * 4);
        }
        __syncthreads();
#pragma unroll
        for (int kk = 0; kk < 16; kk++) {
            u64 aP[4], bP[2];
#pragma unroll
            for (int i = 0; i < 4; i++) aP[i] = pack2_dup(As[kk][ty + 16 * i]);
#pragma unroll
            for (int jp = 0; jp < 2; jp++) bP[jp] = *(const u64*)&Bs[kk][tx * 2 + 32 * jp];
#pragma unroll
            for (int i = 0; i < 4; i++)
#pragma unroll
                for (int jp = 0; jp < 2; jp++) fma2(acc[i][jp], aP[i], bP[jp]);
        }
        __syncthreads();
    }
#pragma unroll
    for (int i = 0; i < 4; i++)
#pragma unroll
        for (int jp = 0; jp < 2; jp++) {
            float lo, hi; unpack2(lo, hi, acc[i][jp]);
            float2 o; o.x = lo; o.y = hi;
            *(float2*)&Cb[(size_t)(mt * 64 + ty + 16 * i) * N + nt * 64 + tx * 2 + 32 * jp] = o;
        }
}

// =============================================================================
// attn: per-(batch,head) sim -> softmax -> M = attn*Wv
// =============================================================================
__global__ __launch_bounds__(256) void attn_kernel(const float* __restrict__ wqkv) {
    const int h = blockIdx.x, b = blockIdx.y;
    __shared__ float S[64][65];
    __shared__ __align__(16) float Buf[4160];
    const int tid = threadIdx.x, tx = tid & 15, ty = tid >> 4;

    const float* QGb = &g_QG[b][h * 64][0];
    const float* Wk = wqkv + (size_t)(NH + h * 64) * NC;
    const float* Wv = wqkv + (size_t)(2 * NH + h * 64) * NC;
    float* Qs = Buf;
    float* Ks = Buf + 64 * 32;

    float acc[4][4] = {};
    for (int kc = 0; kc < NC; kc += 32) {
#pragma unroll
        for (int it = 0; it < 2; it++) {
            int idx = it * 256 + tid;
            int row = idx >> 3, c4 = idx & 7;
            *(float4*)&Qs[row * 32 + c4 * 4] = *(const float4*)(QGb + (size_t)row * NC + kc + c4 * 4);
            float4 v = *(const float4*)(Wk + (size_t)row * NC + kc + c4 * 4);
            Ks[(c4 * 4 + 0) * 65 + row] = v.x;
            Ks[(c4 * 4 + 1) * 65 + row] = v.y;
            Ks[(c4 * 4 + 2) * 65 + row] = v.z;
            Ks[(c4 * 4 + 3) * 65 + row] = v.w;
        }
        __syncthreads();
#pragma unroll
        for (int kk = 0; kk < 32; kk++) {
            float a[4], bb[4];
#pragma unroll
            for (int i = 0; i < 4; i++) a[i] = Qs[(ty + 16 * i) * 32 + kk];
#pragma unroll
            for (int j = 0; j < 4; j++) bb[j] = Ks[kk * 65 + tx + 16 * j];
#pragma unroll
            for (int i = 0; i < 4; i++)
#pragma unroll
                for (int j = 0; j < 4; j++) acc[i][j] += a[i] * bb[j];
        }
        __syncthreads();
    }
    const float scale = 0.125f;
#pragma unroll
    for (int i = 0; i < 4; i++)
#pragma unroll
        for (int j = 0; j < 4; j++)
            S[ty + 16 * i][tx + 16 * j] = acc[i][j] * scale;
    __syncthreads();

    if (tid < 64) {
        float m = -1e30f;
        for (int j = 0; j < 64; j++) m = fmaxf(m, S[tid][j]);
        float sum = 0.f;
        for (int j = 0; j < 64; j++) {
            float e = expf(S[tid][j] - m);
            S[tid][j] = e; sum += e;
        }
        float inv = 1.f / sum;
        for (int j = 0; j < 64; j++) S[tid][j] *= inv;
    }
    __syncthreads();

    float* Ms = &g_M[b][h * 64][0];
    float* Vs = Buf;
    for (int cc = 0; cc < NC; cc += 64) {
#pragma unroll
        for (int it = 0; it < 4; it++) {
            int idx = it * 256 + tid;
            int row = idx >> 4, c4 = idx & 15;
            *(float4*)&Vs[row * 64 + c4 * 4] = *(const float4*)(Wv + (size_t)row * NC + cc + c4 * 4);
        }
        __syncthreads();
        float o[4][4] = {};
        for (int j = 0; j < 64; j++) {
            float a[4], vv[4];
#pragma unroll
            for (int i = 0; i < 4; i++) a[i] = S[ty + 16 * i][j];
#pragma unroll
            for (int jj = 0; jj < 4; jj++) vv[jj] = Vs[j * 64 + tx + 16 * jj];
#pragma unroll
            for (int i = 0; i < 4; i++)
#pragma unroll
                for (int jj = 0; jj < 4; jj++) o[i][jj] += a[i] * vv[jj];
        }
#pragma unroll
        for (int i = 0; i < 4; i++)
#pragma unroll
            for (int jj = 0; jj < 4; jj++)
                Ms[(size_t)(ty + 16 * i) * NC + cc + tx + 16 * jj] = o[i][jj];
        __syncthreads();
    }
}

// =============================================================================
// final_mma: out[b][co][ns] = P[b]*X[b] + bias. Block 128(co) x 128(ns), K=256.
// A = P fp32 split in-register; B = XT hi/lo bf16. grid (32,2,NB), 256 threads.
// =============================================================================
__global__ __launch_bounds__(256) void final_mma(const float* __restrict__ bias,
                                                 float* __restrict__ out) {
    extern __shared__ __align__(16) __nv_bfloat16 sm[];
    __nv_bfloat16* Ah = sm;
    __nv_bfloat16* Al = sm + TILE_E;
    __nv_bfloat16* Bh = sm + 2 * TILE_E;
    __nv_bfloat16* Bl = sm + 3 * TILE_E;

    const int nt = blockIdx.x, mt = blockIdx.y, b = blockIdx.z;
    const int tid = threadIdx.x, lane = tid & 31, wid = tid >> 5;
    const int wm = wid >> 2, wn = wid & 3;

    const u32 aHb = smem_u32(Ah), aLb = smem_u32(Al);
    const u32 bHb = smem_u32(Bh), bLb = smem_u32(Bl);
    const int g = lane >> 3, r8 = lane & 7;
    const int offA = (r8 + (g & 1) * 8) * LDW + (g >> 1) * 8;
    const int offB = (r8 + (g >> 1) * 8) * LDW + (g & 1) * 8;

    const float* Pb = &g_P[b][mt * 128][0];
    const __nv_bfloat16* XTh = &g_XThi[b][nt * 128][0];
    const __nv_bfloat16* XTl = &g_XTlo[b][nt * 128][0];

    float acc[4][4][4] = {};

    for (int c = 0; c < 4; c++) {                 // K=256, chunks of 64
        const int k0 = c * 64;
        {   // A: P 128 rows x 64 fp32 -> split bf16
            const int r0 = tid >> 4, kc4 = tid & 15;
#pragma unroll
            for (int i = 0; i < 8; i++) {
                int row = r0 + 16 * i;
                float4 v = *(const float4*)(Pb + (size_t)row * NC + k0 + kc4 * 4);
                u64 hv, lv; split4(v, hv, lv);
                *(u64*)&Ah[row * LDW + kc4 * 4] = hv;
                *(u64*)&Al[row * LDW + kc4 * 4] = lv;
            }
        }
        {   // B: XT hi/lo 128 rows x 64 bf16
            const int rB = tid >> 3, u = tid & 7;
#pragma unroll
            for (int i = 0; i < 4; i++) {
                int row = rB + 32 * i;
                *(uint4*)&Bh[row * LDW + u * 8] = *(const uint4*)&XTh[(size_t)row * NC + k0 + u * 8];
                *(uint4*)&Bl[row * LDW + u * 8] = *(const uint4*)&XTl[(size_t)row * NC + k0 + u * 8];
            }
        }
        __syncthreads();
#pragma unroll
        for (int ks = 0; ks < 4; ks++) {
            u32 ah[4][4], al[4][4], bh[2][4], bl[2][4];
#pragma unroll
            for (int mf = 0; mf < 4; mf++) {
                u32 o = 2u * (u32)(offA + (wm * 64 + mf * 16) * LDW + ks * 16);
                ldsm4(ah[mf], aHb + o);
                ldsm4(al[mf], aLb + o);
            }
#pragma unroll
            for (int p = 0; p < 2; p++) {
                u32 o = 2u * (u32)(offB + (wn * 32 + p * 16) * LDW + ks * 16);
                ldsm4(bh[p], bHb + o);
                ldsm4(bl[p], bLb + o);
            }
#pragma unroll
            for (int mf = 0; mf < 4; mf++)
#pragma unroll
                for (int p = 0; p < 2; p++)
#pragma unroll
                    for (int hh = 0; hh < 2; hh++) {
                        int nb = p * 2 + hh;
                        mma_bf16(acc[mf][nb], ah[mf], &bh[p][hh * 2]);
                        mma_bf16(acc[mf][nb], ah[mf], &bl[p][hh * 2]);
                        mma_bf16(acc[mf][nb], al[mf], &bh[p][hh * 2]);
                    }
        }
        __syncthreads();
    }

    const int coB = mt * 128 + wm * 64 + (lane >> 2);
    const int nsB = nt * 128 + wn * 32 + 2 * (lane & 3);
#pragma unroll
    for (int mf = 0; mf < 4; mf++) {
        int co = coB + mf * 16;
        float bv0 = bias[co], bv1 = bias[co + 8];
        float* row0 = out + ((size_t)b * NC + co) * NS;
        float* row1 = out + ((size_t)b * NC + co + 8) * NS;
#pragma unroll
        for (int nb = 0; nb < 4; nb++) {
            int cc = nsB + nb * 8;
            float2 v0; v0.x = acc[mf][nb][0] + bv0; v0.y = acc[mf][nb][1] + bv0;
            float2 v1; v1.x = acc[mf][nb][2] + bv1; v1.y = acc[mf][nb][3] + bv1;
            *(float2*)&row0[cc] = v0;
            *(float2*)&row1[cc] = v1;
        }
    }
}

// =============================================================================
extern "C" void kernel_launch(void* const* d_in, const int* in_sizes, int n_in,
                              void* d_out, int out_size) {
    (void)in_sizes; (void)n_in; (void)out_size;
    const float* x     = (const float*)d_in[0];
    const float* w_qkv = (const float*)d_in[1];
    const float* w_out = (const float*)d_in[2];
    const float* b_out = (const float*)d_in[3];
    float* out = (float*)d_out;

    cudaFuncSetAttribute(gram_mma, cudaFuncAttributeMaxDynamicSharedMemorySize, MM_SMEM);
    cudaFuncSetAttribute(final_mma, cudaFuncAttributeMaxDynamicSharedMemorySize, MM_SMEM);

    gram_mma<<<dim3(4, 2, NB), 256, MM_SMEM>>>(x);
    convert_xt<<<dim3(64, 4, NB), 256>>>(x);
    reduce_g_kernel<<<NB * NC * NC / 4 / 256, 256>>>();
    gemm64_kernel<0><<<dim3(4, 8, NB), 256>>>(w_qkv);
    attn_kernel<<<dim3(NHEADS, NB), 256>>>(w_qkv);
    gemm64_kernel<1><<<dim3(4, 4, NB), 256>>>(w_out);
    final_mma<<<dim3(32, 2, NB), 256, MM_SMEM>>>(b_out, out);
}

// round 10
// speedup vs baseline: 1.6396x; 1.0771x over previous
#include <cuda_runtime.h>
#include <cuda_bf16.h>

#define NB 16
#define NC 256
#define NS 4096
#define NH 512
#define NHEADS 8

typedef unsigned long long u64;
typedef unsigned int u32;
typedef unsigned short u16;

// ---------------- scratch (static device memory, 16B-aligned) ----------------
__device__ __align__(16) float g_Gpart[2][NB][NC][NC];       // 8 MB
__device__ __align__(16) float g_G[NB][NC][NC];              // 4 MB
__device__ __align__(16) float g_QG[NB][NH][NC];             // 8 MB
__device__ __align__(16) float g_M[NB][NH][NC];              // 8 MB
__device__ __align__(16) float g_P[NB][NC][NC];              // 4 MB
__device__ __align__(16) __nv_bfloat16 g_XThi[NB][NS][NC];   // 32 MB
__device__ __align__(16) __nv_bfloat16 g_XTlo[NB][NS][NC];   // 32 MB

// ---------------- helpers ----------------------------------------------------
__device__ __forceinline__ u32 smem_u32(const void* p) {
    u32 a;
    asm("{ .reg .u64 t; cvta.to.shared.u64 t, %1; cvt.u32.u64 %0, t; }" : "=r"(a) : "l"(p));
    return a;
}
// split fp32x4 -> 4 bf16 hi (packed u64) + 4 bf16 lo (packed u64)
__device__ __forceinline__ void split4(float4 v, u64& hv, u64& lv) {
    __nv_bfloat16 h0 = __float2bfloat16(v.x), h1 = __float2bfloat16(v.y);
    __nv_bfloat16 h2 = __float2bfloat16(v.z), h3 = __float2bfloat16(v.w);
    __nv_bfloat16 l0 = __float2bfloat16(v.x - __bfloat162float(h0));
    __nv_bfloat16 l1 = __float2bfloat16(v.y - __bfloat162float(h1));
    __nv_bfloat16 l2 = __float2bfloat16(v.z - __bfloat162float(h2));
    __nv_bfloat16 l3 = __float2bfloat16(v.w - __bfloat162float(h3));
    hv = (u64)__bfloat16_as_ushort(h0) | ((u64)__bfloat16_as_ushort(h1) << 16) |
         ((u64)__bfloat16_as_ushort(h2) << 32) | ((u64)__bfloat16_as_ushort(h3) << 48);
    lv = (u64)__bfloat16_as_ushort(l0) | ((u64)__bfloat16_as_ushort(l1) << 16) |
         ((u64)__bfloat16_as_ushort(l2) << 32) | ((u64)__bfloat16_as_ushort(l3) << 48);
}
__device__ __forceinline__ void split1(float v, __nv_bfloat16& h, __nv_bfloat16& l) {
    h = __float2bfloat16(v);
    l = __float2bfloat16(v - __bfloat162float(h));
}
__device__ __forceinline__ void ldsm4(u32* r, u32 addr) {
    asm volatile("ldmatrix.sync.aligned.m8n8.x4.shared.b16 {%0,%1,%2,%3}, [%4];"
                 : "=r"(r[0]), "=r"(r[1]), "=r"(r[2]), "=r"(r[3]) : "r"(addr));
}
__device__ __forceinline__ void mma_bf16(float* d, const u32* a, const u32* b) {
    asm volatile("mma.sync.aligned.m16n8k16.row.col.f32.bf16.bf16.f32 "
        "{%0,%1,%2,%3}, {%4,%5,%6,%7}, {%8,%9}, {%0,%1,%2,%3};"
        : "+f"(d[0]), "+f"(d[1]), "+f"(d[2]), "+f"(d[3])
        : "r"(a[0]), "r"(a[1]), "r"(a[2]), "r"(a[3]), "r"(b[0]), "r"(b[1]));
}

#define LDW 72                       // bf16 elems per smem row (64 + 8 pad; 144 B = 9*16)
#define TILE_E (128 * LDW)           // 9216 elems
#define MM_SMEM (4 * TILE_E * 2)     // 73728 bytes

// =============================================================================
// gram_mma: Gpart[s][b][bi*128..][bj*128..] = Xstrip_bi * Xstrip_bj^T
// over K half s (2048). 3-term bf16 split. grid (4,2,NB), 256 threads.
// =============================================================================
__global__ __launch_bounds__(256) void gram_mma(const float* __restrict__ x) {
    extern __shared__ __align__(16) __nv_bfloat16 sm[];
    __nv_bfloat16* Ah = sm;
    __nv_bfloat16* Al = sm + TILE_E;
    __nv_bfloat16* Bh = sm + 2 * TILE_E;
    __nv_bfloat16* Bl = sm + 3 * TILE_E;

    const int bi = blockIdx.x >> 1, bj = blockIdx.x & 1;
    const int s = blockIdx.y, b = blockIdx.z;
    const int tid = threadIdx.x, lane = tid & 31, wid = tid >> 5;
    const int wm = wid >> 2, wn = wid & 3;       // 2 x 4 warp grid, 64x32 tiles
    const float* Xb = x + (size_t)b * NC * NS;

    const u32 aHb = smem_u32(Ah), aLb = smem_u32(Al);
    const u32 bHb = smem_u32(Bh), bLb = smem_u32(Bl);
    const int g = lane >> 3, r8 = lane & 7;
    const int offA = (r8 + (g & 1) * 8) * LDW + (g >> 1) * 8;   // A ldmatrix lane offset
    const int offB = (r8 + (g >> 1) * 8) * LDW + (g & 1) * 8;   // B ldmatrix lane offset

    float acc[4][4][4] = {};   // [mfrag][nblk][reg]

    const int r0 = tid >> 4, kc4 = tid & 15;
    for (int c = 0; c < 32; c++) {               // 32 chunks of k=64
        const int k0 = s * 2048 + c * 64;
#pragma unroll
        for (int i = 0; i < 8; i++) {
            int row = r0 + 16 * i;
            float4 va = *(const float4*)(Xb + (size_t)(bi * 128 + row) * NS + k0 + kc4 * 4);
            u64 hv, lv; split4(va, hv, lv);
            *(u64*)&Ah[row * LDW + kc4 * 4] = hv;
            *(u64*)&Al[row * LDW + kc4 * 4] = lv;
            float4 vb = *(const float4*)(Xb + (size_t)(bj * 128 + row) * NS + k0 + kc4 * 4);
            split4(vb, hv, lv);
            *(u64*)&Bh[row * LDW + kc4 * 4] = hv;
            *(u64*)&Bl[row * LDW + kc4 * 4] = lv;
        }
        __syncthreads();
#pragma unroll
        for (int ks = 0; ks < 4; ks++) {
            u32 ah[4][4], al[4][4], bh[2][4], bl[2][4];
#pragma unroll
            for (int mf = 0; mf < 4; mf++) {
                u32 o = 2u * (u32)(offA + (wm * 64 + mf * 16) * LDW + ks * 16);
                ldsm4(ah[mf], aHb + o);
                ldsm4(al[mf], aLb + o);
            }
#pragma unroll
            for (int p = 0; p < 2; p++) {
                u32 o = 2u * (u32)(offB + (wn * 32 + p * 16) * LDW + ks * 16);
                ldsm4(bh[p], bHb + o);
                ldsm4(bl[p], bLb + o);
            }
#pragma unroll
            for (int mf = 0; mf < 4; mf++)
#pragma unroll
                for (int p = 0; p < 2; p++)
#pragma unroll
                    for (int hh = 0; hh < 2; hh++) {
                        int nb = p * 2 + hh;
                        mma_bf16(acc[mf][nb], ah[mf], &bh[p][hh * 2]);
                        mma_bf16(acc[mf][nb], ah[mf], &bl[p][hh * 2]);
                        mma_bf16(acc[mf][nb], al[mf], &bh[p][hh * 2]);
                    }
        }
        __syncthreads();
    }

    float* Gp = &g_Gpart[s][b][0][0];
    const int re = bi * 128 + wm * 64 + (lane >> 2);
    const int ce = bj * 128 + wn * 32 + 2 * (lane & 3);
#pragma unroll
    for (int mf = 0; mf < 4; mf++)
#pragma unroll
        for (int nb = 0; nb < 4; nb++) {
            int rr = re + mf * 16, cc = ce + nb * 8;
            float2 v0; v0.x = acc[mf][nb][0]; v0.y = acc[mf][nb][1];
            float2 v1; v1.x = acc[mf][nb][2]; v1.y = acc[mf][nb][3];
            *(float2*)&Gp[(size_t)rr * NC + cc] = v0;
            *(float2*)&Gp[(size_t)(rr + 8) * NC + cc] = v1;
        }
}

// =============================================================================
// convert_xt: X[b][c][ns] fp32 -> XT hi/lo [b][ns][c] bf16. grid (64,4,NB), 256t
// =============================================================================
__global__ __launch_bounds__(256) void convert_xt(const float* __restrict__ x) {
    __shared__ __align__(16) float T[64][68];
    const int ns0 = blockIdx.x * 64, c0 = blockIdx.y * 64, b = blockIdx.z;
    const int tid = threadIdx.x;
    {
        int r = tid >> 2, j = tid & 3;
        const float* src = x + ((size_t)b * NC + c0 + r) * NS + ns0 + j * 16;
        *(float4*)&T[r][j * 16 + 0] = *(const float4*)(src + 0);
        *(float4*)&T[r][j * 16 + 4] = *(const float4*)(src + 4);
        *(float4*)&T[r][j * 16 + 8] = *(const float4*)(src + 8);
        *(float4*)&T[r][j * 16 + 12] = *(const float4*)(src + 12);
    }
    __syncthreads();
    {
        int rn = tid >> 2, j = tid & 3;
        u32 hw[8], lw[8];
#pragma unroll
        for (int kk = 0; kk < 8; kk++) {
            float v0 = T[j * 16 + 2 * kk][rn];
            float v1 = T[j * 16 + 2 * kk + 1][rn];
            __nv_bfloat16 h0, l0, h1, l1;
            split1(v0, h0, l0);
            split1(v1, h1, l1);
            hw[kk] = (u32)__bfloat16_as_ushort(h0) | ((u32)__bfloat16_as_ushort(h1) << 16);
            lw[kk] = (u32)__bfloat16_as_ushort(l0) | ((u32)__bfloat16_as_ushort(l1) << 16);
        }
        uint4* dh = (uint4*)&g_XThi[b][ns0 + rn][c0 + j * 16];
        uint4* dl = (uint4*)&g_XTlo[b][ns0 + rn][c0 + j * 16];
        dh[0] = make_uint4(hw[0], hw[1], hw[2], hw[3]);
        dh[1] = make_uint4(hw[4], hw[5], hw[6], hw[7]);
        dl[0] = make_uint4(lw[0], lw[1], lw[2], lw[3]);
        dl[1] = make_uint4(lw[4], lw[5], lw[6], lw[7]);
    }
}

// =============================================================================
// reduce: G = Gpart[0] + Gpart[1]
// =============================================================================
__global__ __launch_bounds__(256) void reduce_g_kernel() {
    int i = blockIdx.x * 256 + threadIdx.x;
    const float4* p = (const float4*)g_Gpart;
    const int stride = NB * NC * NC / 4;
    float4 a = p[i], c = p[stride + i];
    a.x += c.x; a.y += c.y; a.z += c.z; a.w += c.w;
    ((float4*)g_G)[i] = a;
}

// =============================================================================
// gemm_tc: tensor-core 3-term-split GEMM for the middle chain.
// MODE 0: QG = Wq * G   (A = w_qkv rows 0..511 [m][k], B = G rows (symmetric!)
//                        [n][k], both k-contiguous fp32, split in-fill). K=256.
//                        grid (2 n, 4 m, NB).
// MODE 1: P = W_out * M (A = w_out [m][k]; B = M [k][n] -> transposed split
//                        fill). K=512. grid (2 n, 2 m, NB).
// Block 128(m) x 128(n), k-chunk 64, 256 threads. C fp32 row-major ld=256.
// =============================================================================
template <int MODE>
__global__ __launch_bounds__(256) void gemm_tc(const float* __restrict__ W) {
    extern __shared__ __align__(16) __nv_bfloat16 sm[];
    __nv_bfloat16* Ah = sm;
    __nv_bfloat16* Al = sm + TILE_E;
    __nv_bfloat16* Bh = sm + 2 * TILE_E;
    __nv_bfloat16* Bl = sm + 3 * TILE_E;

    constexpr int K = (MODE == 0) ? 256 : 512;
    const int nt = blockIdx.x, mt = blockIdx.y, b = blockIdx.z;
    const int tid = threadIdx.x, lane = tid & 31, wid = tid >> 5;
    const int wm = wid >> 2, wn = wid & 3;

    const u32 aHb = smem_u32(Ah), aLb = smem_u32(Al);
    const u32 bHb = smem_u32(Bh), bLb = smem_u32(Bl);
    const int g = lane >> 3, r8 = lane & 7;
    const int offA = (r8 + (g & 1) * 8) * LDW + (g >> 1) * 8;
    const int offB = (r8 + (g >> 1) * 8) * LDW + (g & 1) * 8;

    const float* Ab = W + (size_t)(mt * 128) * K;
    const float* Bb = (MODE == 0) ? &g_G[b][0][0] : &g_M[b][0][0];
    float* Cb = (MODE == 0) ? &g_QG[b][0][0] : &g_P[b][0][0];

    float acc[4][4][4] = {};

    for (int c = 0; c < K / 64; c++) {
        const int k0 = c * 64;
        {   // A fill: 128 rows x 64 fp32, k-contiguous -> split bf16
            const int r0 = tid >> 4, kc4 = tid & 15;
#pragma unroll
            for (int i = 0; i < 8; i++) {
                int row = r0 + 16 * i;
                float4 v = *(const float4*)(Ab + (size_t)row * K + k0 + kc4 * 4);
                u64 hv, lv; split4(v, hv, lv);
                *(u64*)&Ah[row * LDW + kc4 * 4] = hv;
                *(u64*)&Al[row * LDW + kc4 * 4] = lv;
            }
        }
        if (MODE == 0) {   // B fill: G rows nt*128.., k-contiguous (symmetry)
            const int r0 = tid >> 4, kc4 = tid & 15;
#pragma unroll
            for (int i = 0; i < 8; i++) {
                int row = r0 + 16 * i;
                float4 v = *(const float4*)(Bb + (size_t)(nt * 128 + row) * K + k0 + kc4 * 4);
                u64 hv, lv; split4(v, hv, lv);
                *(u64*)&Bh[row * LDW + kc4 * 4] = hv;
                *(u64*)&Bl[row * LDW + kc4 * 4] = lv;
            }
        } else {           // B fill: M [k][256] -> Bs[n][k] transposed split
            const int kl = tid >> 2, nseg = tid & 3;
            const float* src = Bb + (size_t)(k0 + kl) * NC + nt * 128 + nseg * 32;
#pragma unroll
            for (int j = 0; j < 8; j++) {
                float4 v = *(const float4*)(src + j * 4);
                int n = nseg * 32 + j * 4;
                __nv_bfloat16 h, l;
                split1(v.x, h, l); Bh[(n + 0) * LDW + kl] = h; Bl[(n + 0) * LDW + kl] = l;
                split1(v.y, h, l); Bh[(n + 1) * LDW + kl] = h; Bl[(n + 1) * LDW + kl] = l;
                split1(v.z, h, l); Bh[(n + 2) * LDW + kl] = h; Bl[(n + 2) * LDW + kl] = l;
                split1(v.w, h, l); Bh[(n + 3) * LDW + kl] = h; Bl[(n + 3) * LDW + kl] = l;
            }
        }
        __syncthreads();
#pragma unroll
        for (int ks = 0; ks < 4; ks++) {
            u32 ah[4][4], al[4][4], bh[2][4], bl[2][4];
#pragma unroll
            for (int mf = 0; mf < 4; mf++) {
                u32 o = 2u * (u32)(offA + (wm * 64 + mf * 16) * LDW + ks * 16);
                ldsm4(ah[mf], aHb + o);
                ldsm4(al[mf], aLb + o);
            }
#pragma unroll
            for (int p = 0; p < 2; p++) {
                u32 o = 2u * (u32)(offB + (wn * 32 + p * 16) * LDW + ks * 16);
                ldsm4(bh[p], bHb + o);
                ldsm4(bl[p], bLb + o);
            }
#pragma unroll
            for (int mf = 0; mf < 4; mf++)
#pragma unroll
                for (int p = 0; p < 2; p++)
#pragma unroll
                    for (int hh = 0; hh < 2; hh++) {
                        int nb = p * 2 + hh;
                        mma_bf16(acc[mf][nb], ah[mf], &bh[p][hh * 2]);
                        mma_bf16(acc[mf][nb], ah[mf], &bl[p][hh * 2]);
                        mma_bf16(acc[mf][nb], al[mf], &bh[p][hh * 2]);
                    }
        }
        __syncthreads();
    }

    const int mB = mt * 128 + wm * 64 + (lane >> 2);
    const int nB = nt * 128 + wn * 32 + 2 * (lane & 3);
#pragma unroll
    for (int mf = 0; mf < 4; mf++) {
        int r = mB + mf * 16;
#pragma unroll
        for (int nb = 0; nb < 4; nb++) {
            int cc = nB + nb * 8;
            float2 v0; v0.x = acc[mf][nb][0]; v0.y = acc[mf][nb][1];
            float2 v1; v1.x = acc[mf][nb][2]; v1.y = acc[mf][nb][3];
            *(float2*)&Cb[(size_t)r * NC + cc] = v0;
            *(float2*)&Cb[(size_t)(r + 8) * NC + cc] = v1;
        }
    }
}

// =============================================================================
// attn: per-(batch,head) sim -> softmax -> M = attn*Wv  (unchanged)
// =============================================================================
__global__ __launch_bounds__(256) void attn_kernel(const float* __restrict__ wqkv) {
    const int h = blockIdx.x, b = blockIdx.y;
    __shared__ float S[64][65];
    __shared__ __align__(16) float Buf[4160];
    const int tid = threadIdx.x, tx = tid & 15, ty = tid >> 4;

    const float* QGb = &g_QG[b][h * 64][0];
    const float* Wk = wqkv + (size_t)(NH + h * 64) * NC;
    const float* Wv = wqkv + (size_t)(2 * NH + h * 64) * NC;
    float* Qs = Buf;
    float* Ks = Buf + 64 * 32;

    float acc[4][4] = {};
    for (int kc = 0; kc < NC; kc += 32) {
#pragma unroll
        for (int it = 0; it < 2; it++) {
            int idx = it * 256 + tid;
            int row = idx >> 3, c4 = idx & 7;
            *(float4*)&Qs[row * 32 + c4 * 4] = *(const float4*)(QGb + (size_t)row * NC + kc + c4 * 4);
            float4 v = *(const float4*)(Wk + (size_t)row * NC + kc + c4 * 4);
            Ks[(c4 * 4 + 0) * 65 + row] = v.x;
            Ks[(c4 * 4 + 1) * 65 + row] = v.y;
            Ks[(c4 * 4 + 2) * 65 + row] = v.z;
            Ks[(c4 * 4 + 3) * 65 + row] = v.w;
        }
        __syncthreads();
#pragma unroll
        for (int kk = 0; kk < 32; kk++) {
            float a[4], bb[4];
#pragma unroll
            for (int i = 0; i < 4; i++) a[i] = Qs[(ty + 16 * i) * 32 + kk];
#pragma unroll
            for (int j = 0; j < 4; j++) bb[j] = Ks[kk * 65 + tx + 16 * j];
#pragma unroll
            for (int i = 0; i < 4; i++)
#pragma unroll
                for (int j = 0; j < 4; j++) acc[i][j] += a[i] * bb[j];
        }
        __syncthreads();
    }
    const float scale = 0.125f;
#pragma unroll
    for (int i = 0; i < 4; i++)
#pragma unroll
        for (int j = 0; j < 4; j++)
            S[ty + 16 * i][tx + 16 * j] = acc[i][j] * scale;
    __syncthreads();

    if (tid < 64) {
        float m = -1e30f;
        for (int j = 0; j < 64; j++) m = fmaxf(m, S[tid][j]);
        float sum = 0.f;
        for (int j = 0; j < 64; j++) {
            float e = expf(S[tid][j] - m);
            S[tid][j] = e; sum += e;
        }
        float inv = 1.f / sum;
        for (int j = 0; j < 64; j++) S[tid][j] *= inv;
    }
    __syncthreads();

    float* Ms = &g_M[b][h * 64][0];
    float* Vs = Buf;
    for (int cc = 0; cc < NC; cc += 64) {
#pragma unroll
        for (int it = 0; it < 4; it++) {
            int idx = it * 256 + tid;
            int row = idx >> 4, c4 = idx & 15;
            *(float4*)&Vs[row * 64 + c4 * 4] = *(const float4*)(Wv + (size_t)row * NC + cc + c4 * 4);
        }
        __syncthreads();
        float o[4][4] = {};
        for (int j = 0; j < 64; j++) {
            float a[4], vv[4];
#pragma unroll
            for (int i = 0; i < 4; i++) a[i] = S[ty + 16 * i][j];
#pragma unroll
            for (int jj = 0; jj < 4; jj++) vv[jj] = Vs[j * 64 + tx + 16 * jj];
#pragma unroll
            for (int i = 0; i < 4; i++)
#pragma unroll
                for (int jj = 0; jj < 4; jj++) o[i][jj] += a[i] * vv[jj];
        }
#pragma unroll
        for (int i = 0; i < 4; i++)
#pragma unroll
            for (int jj = 0; jj < 4; jj++)
                Ms[(size_t)(ty + 16 * i) * NC + cc + tx + 16 * jj] = o[i][jj];
        __syncthreads();
    }
}

// =============================================================================
// final_mma: out[b][co][ns] = P[b]*X[b] + bias. Block 128(co) x 128(ns), K=256.
// A = P fp32 split in-register; B = XT hi/lo bf16. grid (32,2,NB), 256 threads.
// =============================================================================
__global__ __launch_bounds__(256) void final_mma(const float* __restrict__ bias,
                                                 float* __restrict__ out) {
    extern __shared__ __align__(16) __nv_bfloat16 sm[];
    __nv_bfloat16* Ah = sm;
    __nv_bfloat16* Al = sm + TILE_E;
    __nv_bfloat16* Bh = sm + 2 * TILE_E;
    __nv_bfloat16* Bl = sm + 3 * TILE_E;

    const int nt = blockIdx.x, mt = blockIdx.y, b = blockIdx.z;
    const int tid = threadIdx.x, lane = tid & 31, wid = tid >> 5;
    const int wm = wid >> 2, wn = wid & 3;

    const u32 aHb = smem_u32(Ah), aLb = smem_u32(Al);
    const u32 bHb = smem_u32(Bh), bLb = smem_u32(Bl);
    const int g = lane >> 3, r8 = lane & 7;
    const int offA = (r8 + (g & 1) * 8) * LDW + (g >> 1) * 8;
    const int offB = (r8 + (g >> 1) * 8) * LDW + (g & 1) * 8;

    const float* Pb = &g_P[b][mt * 128][0];
    const __nv_bfloat16* XTh = &g_XThi[b][nt * 128][0];
    const __nv_bfloat16* XTl = &g_XTlo[b][nt * 128][0];

    float acc[4][4][4] = {};

    for (int c = 0; c < 4; c++) {                 // K=256, chunks of 64
        const int k0 = c * 64;
        {   // A: P 128 rows x 64 fp32 -> split bf16
            const int r0 = tid >> 4, kc4 = tid & 15;
#pragma unroll
            for (int i = 0; i < 8; i++) {
                int row = r0 + 16 * i;
                float4 v = *(const float4*)(Pb + (size_t)row * NC + k0 + kc4 * 4);
                u64 hv, lv; split4(v, hv, lv);
                *(u64*)&Ah[row * LDW + kc4 * 4] = hv;
                *(u64*)&Al[row * LDW + kc4 * 4] = lv;
            }
        }
        {   // B: XT hi/lo 128 rows x 64 bf16
            const int rB = tid >> 3, u = tid & 7;
#pragma unroll
            for (int i = 0; i < 4; i++) {
                int row = rB + 32 * i;
                *(uint4*)&Bh[row * LDW + u * 8] = *(const uint4*)&XTh[(size_t)row * NC + k0 + u * 8];
                *(uint4*)&Bl[row * LDW + u * 8] = *(const uint4*)&XTl[(size_t)row * NC + k0 + u * 8];
            }
        }
        __syncthreads();
#pragma unroll
        for (int ks = 0; ks < 4; ks++) {
            u32 ah[4][4], al[4][4], bh[2][4], bl[2][4];
#pragma unroll
            for (int mf = 0; mf < 4; mf++) {
                u32 o = 2u * (u32)(offA + (wm * 64 + mf * 16) * LDW + ks * 16);
                ldsm4(ah[mf], aHb + o);
                ldsm4(al[mf], aLb + o);
            }
#pragma unroll
            for (int p = 0; p < 2; p++) {
                u32 o = 2u * (u32)(offB + (wn * 32 + p * 16) * LDW + ks * 16);
                ldsm4(bh[p], bHb + o);
                ldsm4(bl[p], bLb + o);
            }
#pragma unroll
            for (int mf = 0; mf < 4; mf++)
#pragma unroll
                for (int p = 0; p < 2; p++)
#pragma unroll
                    for (int hh = 0; hh < 2; hh++) {
                        int nb = p * 2 + hh;
                        mma_bf16(acc[mf][nb], ah[mf], &bh[p][hh * 2]);
                        mma_bf16(acc[mf][nb], ah[mf], &bl[p][hh * 2]);
                        mma_bf16(acc[mf][nb], al[mf], &bh[p][hh * 2]);
                    }
        }
        __syncthreads();
    }

    const int coB = mt * 128 + wm * 64 + (lane >> 2);
    const int nsB = nt * 128 + wn * 32 + 2 * (lane & 3);
#pragma unroll
    for (int mf = 0; mf < 4; mf++) {
        int co = coB + mf * 16;
        float bv0 = bias[co], bv1 = bias[co + 8];
        float* row0 = out + ((size_t)b * NC + co) * NS;
        float* row1 = out + ((size_t)b * NC + co + 8) * NS;
#pragma unroll
        for (int nb = 0; nb < 4; nb++) {
            int cc = nsB + nb * 8;
            float2 v0; v0.x = acc[mf][nb][0] + bv0; v0.y = acc[mf][nb][1] + bv0;
            float2 v1; v1.x = acc[mf][nb][2] + bv1; v1.y = acc[mf][nb][3] + bv1;
            *(float2*)&row0[cc] = v0;
            *(float2*)&row1[cc] = v1;
        }
    }
}

// =============================================================================
extern "C" void kernel_launch(void* const* d_in, const int* in_sizes, int n_in,
                              void* d_out, int out_size) {
    (void)in_sizes; (void)n_in; (void)out_size;
    const float* x     = (const float*)d_in[0];
    const float* w_qkv = (const float*)d_in[1];
    const float* w_out = (const float*)d_in[2];
    const float* b_out = (const float*)d_in[3];
    float* out = (float*)d_out;

    cudaFuncSetAttribute(gram_mma, cudaFuncAttributeMaxDynamicSharedMemorySize, MM_SMEM);
    cudaFuncSetAttribute(final_mma, cudaFuncAttributeMaxDynamicSharedMemorySize, MM_SMEM);
    cudaFuncSetAttribute(gemm_tc<0>, cudaFuncAttributeMaxDynamicSharedMemorySize, MM_SMEM);
    cudaFuncSetAttribute(gemm_tc<1>, cudaFuncAttributeMaxDynamicSharedMemorySize, MM_SMEM);

    gram_mma<<<dim3(4, 2, NB), 256, MM_SMEM>>>(x);
    convert_xt<<<dim3(64, 4, NB), 256>>>(x);
    reduce_g_kernel<<<NB * NC * NC / 4 / 256, 256>>>();
    gemm_tc<0><<<dim3(2, 4, NB), 256, MM_SMEM>>>(w_qkv);
    attn_kernel<<<dim3(NHEADS, NB), 256>>>(w_qkv);
    gemm_tc<1><<<dim3(2, 2, NB), 256, MM_SMEM>>>(w_out);
    final_mma<<<dim3(32, 2, NB), 256, MM_SMEM>>>(b_out, out);
}

// round 11
// speedup vs baseline: 1.7051x; 1.0400x over previous
#include <cuda_runtime.h>
#include <cuda_bf16.h>

#define NB 16
#define NC 256
#define NS 4096
#define NH 512
#define NHEADS 8

typedef unsigned long long u64;
typedef unsigned int u32;
typedef unsigned short u16;

// ---------------- scratch (static device memory, 16B-aligned) ----------------
__device__ __align__(16) float g_Gpart[2][NB][NC][NC];       // 8 MB
__device__ __align__(16) float g_G[NB][NC][NC];              // 4 MB
__device__ __align__(16) float g_QG[NB][NH][NC];             // 8 MB
__device__ __align__(16) float g_M[NB][NH][NC];              // 8 MB
__device__ __align__(16) float g_P[NB][NC][NC];              // 4 MB
__device__ __align__(16) __nv_bfloat16 g_XThi[NB][NS][NC];   // 32 MB  X^T hi
__device__ __align__(16) __nv_bfloat16 g_XTlo[NB][NS][NC];   // 32 MB  X^T lo
__device__ __align__(16) __nv_bfloat16 g_Xhi[NB][NC][NS];    // 32 MB  X hi (k-major)
__device__ __align__(16) __nv_bfloat16 g_Xlo[NB][NC][NS];    // 32 MB  X lo (k-major)

// ---------------- helpers ----------------------------------------------------
__device__ __forceinline__ u32 smem_u32(const void* p) {
    u32 a;
    asm("{ .reg .u64 t; cvta.to.shared.u64 t, %1; cvt.u32.u64 %0, t; }" : "=r"(a) : "l"(p));
    return a;
}
// split fp32x4 -> 4 bf16 hi (packed u64) + 4 bf16 lo (packed u64)
__device__ __forceinline__ void split4(float4 v, u64& hv, u64& lv) {
    __nv_bfloat16 h0 = __float2bfloat16(v.x), h1 = __float2bfloat16(v.y);
    __nv_bfloat16 h2 = __float2bfloat16(v.z), h3 = __float2bfloat16(v.w);
    __nv_bfloat16 l0 = __float2bfloat16(v.x - __bfloat162float(h0));
    __nv_bfloat16 l1 = __float2bfloat16(v.y - __bfloat162float(h1));
    __nv_bfloat16 l2 = __float2bfloat16(v.z - __bfloat162float(h2));
    __nv_bfloat16 l3 = __float2bfloat16(v.w - __bfloat162float(h3));
    hv = (u64)__bfloat16_as_ushort(h0) | ((u64)__bfloat16_as_ushort(h1) << 16) |
         ((u64)__bfloat16_as_ushort(h2) << 32) | ((u64)__bfloat16_as_ushort(h3) << 48);
    lv = (u64)__bfloat16_as_ushort(l0) | ((u64)__bfloat16_as_ushort(l1) << 16) |
         ((u64)__bfloat16_as_ushort(l2) << 32) | ((u64)__bfloat16_as_ushort(l3) << 48);
}
__device__ __forceinline__ void split1(float v, __nv_bfloat16& h, __nv_bfloat16& l) {
    h = __float2bfloat16(v);
    l = __float2bfloat16(v - __bfloat162float(h));
}
__device__ __forceinline__ void ldsm4(u32* r, u32 addr) {
    asm volatile("ldmatrix.sync.aligned.m8n8.x4.shared.b16 {%0,%1,%2,%3}, [%4];"
                 : "=r"(r[0]), "=r"(r[1]), "=r"(r[2]), "=r"(r[3]) : "r"(addr));
}
__device__ __forceinline__ void mma_bf16(float* d, const u32* a, const u32* b) {
    asm volatile("mma.sync.aligned.m16n8k16.row.col.f32.bf16.bf16.f32 "
        "{%0,%1,%2,%3}, {%4,%5,%6,%7}, {%8,%9}, {%0,%1,%2,%3};"
        : "+f"(d[0]), "+f"(d[1]), "+f"(d[2]), "+f"(d[3])
        : "r"(a[0]), "r"(a[1]), "r"(a[2]), "r"(a[3]), "r"(b[0]), "r"(b[1]));
}

#define LDW 72                       // bf16 elems per smem row (144 B = 9*16)
#define TILE_E (128 * LDW)           // 9216 elems
#define MM_SMEM (4 * TILE_E * 2)     // 73728 bytes
#define NT 512                       // threads per mma CTA (16 warps, 4x4 of 32x32)

// =============================================================================
// convert_x: X fp32 -> Xhi/Xlo bf16 (same [b][c][ns] layout). grid 8192 x 256.
// =============================================================================
__global__ __launch_bounds__(256) void convert_x(const float* __restrict__ x) {
    size_t i = ((size_t)blockIdx.x * 256 + threadIdx.x) * 8;
    float4 v0 = *(const float4*)(x + i);
    float4 v1 = *(const float4*)(x + i + 4);
    u64 h0, l0, h1, l1;
    split4(v0, h0, l0);
    split4(v1, h1, l1);
    *(ulonglong2*)((__nv_bfloat16*)g_Xhi + i) = make_ulonglong2(h0, h1);
    *(ulonglong2*)((__nv_bfloat16*)g_Xlo + i) = make_ulonglong2(l0, l1);
}

// =============================================================================
// gram_mma: Gpart[s][b] 128x128 block (bi,bj) over K half s. Fill = uint4 copy
// from pre-split Xhi/Xlo; diag blocks alias B to A. grid (4,2,NB), 512 thr.
// =============================================================================
__global__ __launch_bounds__(NT) void gram_mma() {
    extern __shared__ __align__(16) __nv_bfloat16 sm[];
    __nv_bfloat16* Ah = sm;
    __nv_bfloat16* Al = sm + TILE_E;
    __nv_bfloat16* Bh = sm + 2 * TILE_E;
    __nv_bfloat16* Bl = sm + 3 * TILE_E;

    const int bi = blockIdx.x >> 1, bj = blockIdx.x & 1;
    const int s = blockIdx.y, b = blockIdx.z;
    const int tid = threadIdx.x, lane = tid & 31, wid = tid >> 5;
    const int wm = wid >> 2, wn = wid & 3;        // 4x4 warps, 32x32 tiles
    const bool diag = (bi == bj);

    const u32 aHb = smem_u32(Ah), aLb = smem_u32(Al);
    const u32 bHb = diag ? aHb : smem_u32(Bh), bLb = diag ? aLb : smem_u32(Bl);
    const int g = lane >> 3, r8 = lane & 7;
    const int offA = (r8 + (g & 1) * 8) * LDW + (g >> 1) * 8;
    const int offB = (r8 + (g >> 1) * 8) * LDW + (g & 1) * 8;

    float acc[2][4][4] = {};   // [mfrag][nblk][reg]

    const int r = tid >> 2, sg = tid & 3;         // 4 threads/row, 2 uint4 each
    for (int c = 0; c < 32; c++) {
        const int k0 = s * 2048 + c * 64;
        {
            const __nv_bfloat16* srcH = &g_Xhi[b][bi * 128 + r][k0];
            const __nv_bfloat16* srcL = &g_Xlo[b][bi * 128 + r][k0];
            *(uint4*)&Ah[r * LDW + (2 * sg) * 8]     = *(const uint4*)(srcH + (2 * sg) * 8);
            *(uint4*)&Ah[r * LDW + (2 * sg + 1) * 8] = *(const uint4*)(srcH + (2 * sg + 1) * 8);
            *(uint4*)&Al[r * LDW + (2 * sg) * 8]     = *(const uint4*)(srcL + (2 * sg) * 8);
            *(uint4*)&Al[r * LDW + (2 * sg + 1) * 8] = *(const uint4*)(srcL + (2 * sg + 1) * 8);
            if (!diag) {
                const __nv_bfloat16* sH = &g_Xhi[b][bj * 128 + r][k0];
                const __nv_bfloat16* sL = &g_Xlo[b][bj * 128 + r][k0];
                *(uint4*)&Bh[r * LDW + (2 * sg) * 8]     = *(const uint4*)(sH + (2 * sg) * 8);
                *(uint4*)&Bh[r * LDW + (2 * sg + 1) * 8] = *(const uint4*)(sH + (2 * sg + 1) * 8);
                *(uint4*)&Bl[r * LDW + (2 * sg) * 8]     = *(const uint4*)(sL + (2 * sg) * 8);
                *(uint4*)&Bl[r * LDW + (2 * sg + 1) * 8] = *(const uint4*)(sL + (2 * sg + 1) * 8);
            }
        }
        __syncthreads();
#pragma unroll
        for (int ks = 0; ks < 4; ks++) {
            u32 ah[2][4], al[2][4], bh[2][4], bl[2][4];
#pragma unroll
            for (int mf = 0; mf < 2; mf++) {
                u32 o = 2u * (u32)(offA + (wm * 32 + mf * 16) * LDW + ks * 16);
                ldsm4(ah[mf], aHb + o);
                ldsm4(al[mf], aLb + o);
            }
#pragma unroll
            for (int p = 0; p < 2; p++) {
                u32 o = 2u * (u32)(offB + (wn * 32 + p * 16) * LDW + ks * 16);
                ldsm4(bh[p], bHb + o);
                ldsm4(bl[p], bLb + o);
            }
#pragma unroll
            for (int mf = 0; mf < 2; mf++)
#pragma unroll
                for (int p = 0; p < 2; p++)
#pragma unroll
                    for (int hh = 0; hh < 2; hh++) {
                        int nb = p * 2 + hh;
                        mma_bf16(acc[mf][nb], ah[mf], &bh[p][hh * 2]);
                        mma_bf16(acc[mf][nb], ah[mf], &bl[p][hh * 2]);
                        mma_bf16(acc[mf][nb], al[mf], &bh[p][hh * 2]);
                    }
        }
        __syncthreads();
    }

    float* Gp = &g_Gpart[s][b][0][0];
    const int re = bi * 128 + wm * 32 + (lane >> 2);
    const int ce = bj * 128 + wn * 32 + 2 * (lane & 3);
#pragma unroll
    for (int mf = 0; mf < 2; mf++)
#pragma unroll
        for (int nb = 0; nb < 4; nb++) {
            int rr = re + mf * 16, cc = ce + nb * 8;
            float2 v0; v0.x = acc[mf][nb][0]; v0.y = acc[mf][nb][1];
            float2 v1; v1.x = acc[mf][nb][2]; v1.y = acc[mf][nb][3];
            *(float2*)&Gp[(size_t)rr * NC + cc] = v0;
            *(float2*)&Gp[(size_t)(rr + 8) * NC + cc] = v1;
        }
}

// =============================================================================
// convert_xt: X fp32 -> XT hi/lo [b][ns][c] bf16. grid (64,4,NB), 256 thr.
// =============================================================================
__global__ __launch_bounds__(256) void convert_xt(const float* __restrict__ x) {
    __shared__ __align__(16) float T[64][68];
    const int ns0 = blockIdx.x * 64, c0 = blockIdx.y * 64, b = blockIdx.z;
    const int tid = threadIdx.x;
    {
        int r = tid >> 2, j = tid & 3;
        const float* src = x + ((size_t)b * NC + c0 + r) * NS + ns0 + j * 16;
        *(float4*)&T[r][j * 16 + 0] = *(const float4*)(src + 0);
        *(float4*)&T[r][j * 16 + 4] = *(const float4*)(src + 4);
        *(float4*)&T[r][j * 16 + 8] = *(const float4*)(src + 8);
        *(float4*)&T[r][j * 16 + 12] = *(const float4*)(src + 12);
    }
    __syncthreads();
    {
        int rn = tid >> 2, j = tid & 3;
        u32 hw[8], lw[8];
#pragma unroll
        for (int kk = 0; kk < 8; kk++) {
            float v0 = T[j * 16 + 2 * kk][rn];
            float v1 = T[j * 16 + 2 * kk + 1][rn];
            __nv_bfloat16 h0, l0, h1, l1;
            split1(v0, h0, l0);
            split1(v1, h1, l1);
            hw[kk] = (u32)__bfloat16_as_ushort(h0) | ((u32)__bfloat16_as_ushort(h1) << 16);
            lw[kk] = (u32)__bfloat16_as_ushort(l0) | ((u32)__bfloat16_as_ushort(l1) << 16);
        }
        uint4* dh = (uint4*)&g_XThi[b][ns0 + rn][c0 + j * 16];
        uint4* dl = (uint4*)&g_XTlo[b][ns0 + rn][c0 + j * 16];
        dh[0] = make_uint4(hw[0], hw[1], hw[2], hw[3]);
        dh[1] = make_uint4(hw[4], hw[5], hw[6], hw[7]);
        dl[0] = make_uint4(lw[0], lw[1], lw[2], lw[3]);
        dl[1] = make_uint4(lw[4], lw[5], lw[6], lw[7]);
    }
}

// =============================================================================
// reduce: G = Gpart[0] + Gpart[1]
// =============================================================================
__global__ __launch_bounds__(256) void reduce_g_kernel() {
    int i = blockIdx.x * 256 + threadIdx.x;
    const float4* p = (const float4*)g_Gpart;
    const int stride = NB * NC * NC / 4;
    float4 a = p[i], c = p[stride + i];
    a.x += c.x; a.y += c.y; a.z += c.z; a.w += c.w;
    ((float4*)g_G)[i] = a;
}

// =============================================================================
// gemm_tc: 3-term-split tensor GEMM, 512 threads, 32x32 warp tiles.
// MODE 0: QG = Wq * G (B = G rows via symmetry, k-contig). K=256, grid (2,4,NB).
// MODE 1: P = W_out * M (B = M [k][n], transposed fill). K=512, grid (2,2,NB).
// =============================================================================
template <int MODE>
__global__ __launch_bounds__(NT) void gemm_tc(const float* __restrict__ W) {
    extern __shared__ __align__(16) __nv_bfloat16 sm[];
    __nv_bfloat16* Ah = sm;
    __nv_bfloat16* Al = sm + TILE_E;
    __nv_bfloat16* Bh = sm + 2 * TILE_E;
    __nv_bfloat16* Bl = sm + 3 * TILE_E;

    constexpr int K = (MODE == 0) ? 256 : 512;
    const int nt = blockIdx.x, mt = blockIdx.y, b = blockIdx.z;
    const int tid = threadIdx.x, lane = tid & 31, wid = tid >> 5;
    const int wm = wid >> 2, wn = wid & 3;

    const u32 aHb = smem_u32(Ah), aLb = smem_u32(Al);
    const u32 bHb = smem_u32(Bh), bLb = smem_u32(Bl);
    const int g = lane >> 3, r8 = lane & 7;
    const int offA = (r8 + (g & 1) * 8) * LDW + (g >> 1) * 8;
    const int offB = (r8 + (g >> 1) * 8) * LDW + (g & 1) * 8;

    const float* Ab = W + (size_t)(mt * 128) * K;
    const float* Bb = (MODE == 0) ? &g_G[b][0][0] : &g_M[b][0][0];
    float* Cb = (MODE == 0) ? &g_QG[b][0][0] : &g_P[b][0][0];

    float acc[2][4][4] = {};

    for (int c = 0; c < K / 64; c++) {
        const int k0 = c * 64;
        {   // A fill: 128 rows x 64 fp32, 4 thr/row, 4 float4 each
            const int r = tid >> 2, sg = tid & 3;
            const float* src = Ab + (size_t)r * K + k0 + sg * 16;
#pragma unroll
            for (int j = 0; j < 4; j++) {
                float4 v = ((const float4*)src)[j];
                u64 hv, lv; split4(v, hv, lv);
                *(u64*)&Ah[r * LDW + sg * 16 + j * 4] = hv;
                *(u64*)&Al[r * LDW + sg * 16 + j * 4] = lv;
            }
        }
        if (MODE == 0) {   // B: G rows (symmetry), k-contiguous
            const int r = tid >> 2, sg = tid & 3;
            const float* src = Bb + (size_t)(nt * 128 + r) * K + k0 + sg * 16;
#pragma unroll
            for (int j = 0; j < 4; j++) {
                float4 v = ((const float4*)src)[j];
                u64 hv, lv; split4(v, hv, lv);
                *(u64*)&Bh[r * LDW + sg * 16 + j * 4] = hv;
                *(u64*)&Bl[r * LDW + sg * 16 + j * 4] = lv;
            }
        } else {           // B: M [k][256] -> transposed split fill
            const int kl = tid >> 3, ns8 = tid & 7;
            const float* src = Bb + (size_t)(k0 + kl) * NC + nt * 128 + ns8 * 16;
#pragma unroll
            for (int j = 0; j < 4; j++) {
                float4 v = ((const float4*)src)[j];
                int n = ns8 * 16 + j * 4;
                __nv_bfloat16 h, l;
                split1(v.x, h, l); Bh[(n + 0) * LDW + kl] = h; Bl[(n + 0) * LDW + kl] = l;
                split1(v.y, h, l); Bh[(n + 1) * LDW + kl] = h; Bl[(n + 1) * LDW + kl] = l;
                split1(v.z, h, l); Bh[(n + 2) * LDW + kl] = h; Bl[(n + 2) * LDW + kl] = l;
                split1(v.w, h, l); Bh[(n + 3) * LDW + kl] = h; Bl[(n + 3) * LDW + kl] = l;
            }
        }
        __syncthreads();
#pragma unroll
        for (int ks = 0; ks < 4; ks++) {
            u32 ah[2][4], al[2][4], bh[2][4], bl[2][4];
#pragma unroll
            for (int mf = 0; mf < 2; mf++) {
                u32 o = 2u * (u32)(offA + (wm * 32 + mf * 16) * LDW + ks * 16);
                ldsm4(ah[mf], aHb + o);
                ldsm4(al[mf], aLb + o);
            }
#pragma unroll
            for (int p = 0; p < 2; p++) {
                u32 o = 2u * (u32)(offB + (wn * 32 + p * 16) * LDW + ks * 16);
                ldsm4(bh[p], bHb + o);
                ldsm4(bl[p], bLb + o);
            }
#pragma unroll
            for (int mf = 0; mf < 2; mf++)
#pragma unroll
                for (int p = 0; p < 2; p++)
#pragma unroll
                    for (int hh = 0; hh < 2; hh++) {
                        int nb = p * 2 + hh;
                        mma_bf16(acc[mf][nb], ah[mf], &bh[p][hh * 2]);
                        mma_bf16(acc[mf][nb], ah[mf], &bl[p][hh * 2]);
                        mma_bf16(acc[mf][nb], al[mf], &bh[p][hh * 2]);
                    }
        }
        __syncthreads();
    }

    const int mB = mt * 128 + wm * 32 + (lane >> 2);
    const int nB = nt * 128 + wn * 32 + 2 * (lane & 3);
#pragma unroll
    for (int mf = 0; mf < 2; mf++) {
        int r = mB + mf * 16;
#pragma unroll
        for (int nb = 0; nb < 4; nb++) {
            int cc = nB + nb * 8;
            float2 v0; v0.x = acc[mf][nb][0]; v0.y = acc[mf][nb][1];
            float2 v1; v1.x = acc[mf][nb][2]; v1.y = acc[mf][nb][3];
            *(float2*)&Cb[(size_t)r * NC + cc] = v0;
            *(float2*)&Cb[(size_t)(r + 8) * NC + cc] = v1;
        }
    }
}

// =============================================================================
// attn: per-(batch,head) sim -> softmax -> M = attn*Wv  (unchanged)
// =============================================================================
__global__ __launch_bounds__(256) void attn_kernel(const float* __restrict__ wqkv) {
    const int h = blockIdx.x, b = blockIdx.y;
    __shared__ float S[64][65];
    __shared__ __align__(16) float Buf[4160];
    const int tid = threadIdx.x, tx = tid & 15, ty = tid >> 4;

    const float* QGb = &g_QG[b][h * 64][0];
    const float* Wk = wqkv + (size_t)(NH + h * 64) * NC;
    const float* Wv = wqkv + (size_t)(2 * NH + h * 64) * NC;
    float* Qs = Buf;
    float* Ks = Buf + 64 * 32;

    float acc[4][4] = {};
    for (int kc = 0; kc < NC; kc += 32) {
#pragma unroll
        for (int it = 0; it < 2; it++) {
            int idx = it * 256 + tid;
            int row = idx >> 3, c4 = idx & 7;
            *(float4*)&Qs[row * 32 + c4 * 4] = *(const float4*)(QGb + (size_t)row * NC + kc + c4 * 4);
            float4 v = *(const float4*)(Wk + (size_t)row * NC + kc + c4 * 4);
            Ks[(c4 * 4 + 0) * 65 + row] = v.x;
            Ks[(c4 * 4 + 1) * 65 + row] = v.y;
            Ks[(c4 * 4 + 2) * 65 + row] = v.z;
            Ks[(c4 * 4 + 3) * 65 + row] = v.w;
        }
        __syncthreads();
#pragma unroll
        for (int kk = 0; kk < 32; kk++) {
            float a[4], bb[4];
#pragma unroll
            for (int i = 0; i < 4; i++) a[i] = Qs[(ty + 16 * i) * 32 + kk];
#pragma unroll
            for (int j = 0; j < 4; j++) bb[j] = Ks[kk * 65 + tx + 16 * j];
#pragma unroll
            for (int i = 0; i < 4; i++)
#pragma unroll
                for (int j = 0; j < 4; j++) acc[i][j] += a[i] * bb[j];
        }
        __syncthreads();
    }
    const float scale = 0.125f;
#pragma unroll
    for (int i = 0; i < 4; i++)
#pragma unroll
        for (int j = 0; j < 4; j++)
            S[ty + 16 * i][tx + 16 * j] = acc[i][j] * scale;
    __syncthreads();

    if (tid < 64) {
        float m = -1e30f;
        for (int j = 0; j < 64; j++) m = fmaxf(m, S[tid][j]);
        float sum = 0.f;
        for (int j = 0; j < 64; j++) {
            float e = expf(S[tid][j] - m);
            S[tid][j] = e; sum += e;
        }
        float inv = 1.f / sum;
        for (int j = 0; j < 64; j++) S[tid][j] *= inv;
    }
    __syncthreads();

    float* Ms = &g_M[b][h * 64][0];
    float* Vs = Buf;
    for (int cc = 0; cc < NC; cc += 64) {
#pragma unroll
        for (int it = 0; it < 4; it++) {
            int idx = it * 256 + tid;
            int row = idx >> 4, c4 = idx & 15;
            *(float4*)&Vs[row * 64 + c4 * 4] = *(const float4*)(Wv + (size_t)row * NC + cc + c4 * 4);
        }
        __syncthreads();
        float o[4][4] = {};
        for (int j = 0; j < 64; j++) {
            float a[4], vv[4];
#pragma unroll
            for (int i = 0; i < 4; i++) a[i] = S[ty + 16 * i][j];
#pragma unroll
            for (int jj = 0; jj < 4; jj++) vv[jj] = Vs[j * 64 + tx + 16 * jj];
#pragma unroll
            for (int i = 0; i < 4; i++)
#pragma unroll
                for (int jj = 0; jj < 4; jj++) o[i][jj] += a[i] * vv[jj];
        }
#pragma unroll
        for (int i = 0; i < 4; i++)
#pragma unroll
            for (int jj = 0; jj < 4; jj++)
                Ms[(size_t)(ty + 16 * i) * NC + cc + tx + 16 * jj] = o[i][jj];
        __syncthreads();
    }
}

// =============================================================================
// final_mma: out = P*X + bias. 128(co) x 128(ns), K=256, 512 threads.
// =============================================================================
__global__ __launch_bounds__(NT) void final_mma(const float* __restrict__ bias,
                                                float* __restrict__ out) {
    extern __shared__ __align__(16) __nv_bfloat16 sm[];
    __nv_bfloat16* Ah = sm;
    __nv_bfloat16* Al = sm + TILE_E;
    __nv_bfloat16* Bh = sm + 2 * TILE_E;
    __nv_bfloat16* Bl = sm + 3 * TILE_E;

    const int nt = blockIdx.x, mt = blockIdx.y, b = blockIdx.z;
    const int tid = threadIdx.x, lane = tid & 31, wid = tid >> 5;
    const int wm = wid >> 2, wn = wid & 3;

    const u32 aHb = smem_u32(Ah), aLb = smem_u32(Al);
    const u32 bHb = smem_u32(Bh), bLb = smem_u32(Bl);
    const int g = lane >> 3, r8 = lane & 7;
    const int offA = (r8 + (g & 1) * 8) * LDW + (g >> 1) * 8;
    const int offB = (r8 + (g >> 1) * 8) * LDW + (g & 1) * 8;

    const float* Pb = &g_P[b][mt * 128][0];
    const __nv_bfloat16* XTh = &g_XThi[b][nt * 128][0];
    const __nv_bfloat16* XTl = &g_XTlo[b][nt * 128][0];

    float acc[2][4][4] = {};

    for (int c = 0; c < 4; c++) {
        const int k0 = c * 64;
        {   // A: P 128 rows x 64 fp32 -> split
            const int r = tid >> 2, sg = tid & 3;
            const float* src = Pb + (size_t)r * NC + k0 + sg * 16;
#pragma unroll
            for (int j = 0; j < 4; j++) {
                float4 v = ((const float4*)src)[j];
                u64 hv, lv; split4(v, hv, lv);
                *(u64*)&Ah[r * LDW + sg * 16 + j * 4] = hv;
                *(u64*)&Al[r * LDW + sg * 16 + j * 4] = lv;
            }
        }
        {   // B: XT hi/lo copy, 128 rows x 64 bf16
            const int r = tid >> 2, sg = tid & 3;
            const __nv_bfloat16* sH = XTh + (size_t)r * NC + k0;
            const __nv_bfloat16* sL = XTl + (size_t)r * NC + k0;
            *(uint4*)&Bh[r * LDW + (2 * sg) * 8]     = *(const uint4*)(sH + (2 * sg) * 8);
            *(uint4*)&Bh[r * LDW + (2 * sg + 1) * 8] = *(const uint4*)(sH + (2 * sg + 1) * 8);
            *(uint4*)&Bl[r * LDW + (2 * sg) * 8]     = *(const uint4*)(sL + (2 * sg) * 8);
            *(uint4*)&Bl[r * LDW + (2 * sg + 1) * 8] = *(const uint4*)(sL + (2 * sg + 1) * 8);
        }
        __syncthreads();
#pragma unroll
        for (int ks = 0; ks < 4; ks++) {
            u32 ah[2][4], al[2][4], bh[2][4], bl[2][4];
#pragma unroll
            for (int mf = 0; mf < 2; mf++) {
                u32 o = 2u * (u32)(offA + (wm * 32 + mf * 16) * LDW + ks * 16);
                ldsm4(ah[mf], aHb + o);
                ldsm4(al[mf], aLb + o);
            }
#pragma unroll
            for (int p = 0; p < 2; p++) {
                u32 o = 2u * (u32)(offB + (wn * 32 + p * 16) * LDW + ks * 16);
                ldsm4(bh[p], bHb + o);
                ldsm4(bl[p], bLb + o);
            }
#pragma unroll
            for (int mf = 0; mf < 2; mf++)
#pragma unroll
                for (int p = 0; p < 2; p++)
#pragma unroll
                    for (int hh = 0; hh < 2; hh++) {
                        int nb = p * 2 + hh;
                        mma_bf16(acc[mf][nb], ah[mf], &bh[p][hh * 2]);
                        mma_bf16(acc[mf][nb], ah[mf], &bl[p][hh * 2]);
                        mma_bf16(acc[mf][nb], al[mf], &bh[p][hh * 2]);
                    }
        }
        __syncthreads();
    }

    const int coB = mt * 128 + wm * 32 + (lane >> 2);
    const int nsB = nt * 128 + wn * 32 + 2 * (lane & 3);
#pragma unroll
    for (int mf = 0; mf < 2; mf++) {
        int co = coB + mf * 16;
        float bv0 = bias[co], bv1 = bias[co + 8];
        float* row0 = out + ((size_t)b * NC + co) * NS;
        float* row1 = out + ((size_t)b * NC + co + 8) * NS;
#pragma unroll
        for (int nb = 0; nb < 4; nb++) {
            int cc = nsB + nb * 8;
            float2 v0; v0.x = acc[mf][nb][0] + bv0; v0.y = acc[mf][nb][1] + bv0;
            float2 v1; v1.x = acc[mf][nb][2] + bv1; v1.y = acc[mf][nb][3] + bv1;
            *(float2*)&row0[cc] = v0;
            *(float2*)&row1[cc] = v1;
        }
    }
}

// =============================================================================
extern "C" void kernel_launch(void* const* d_in, const int* in_sizes, int n_in,
                              void* d_out, int out_size) {
    (void)in_sizes; (void)n_in; (void)out_size;
    const float* x     = (const float*)d_in[0];
    const float* w_qkv = (const float*)d_in[1];
    const float* w_out = (const float*)d_in[2];
    const float* b_out = (const float*)d_in[3];
    float* out = (float*)d_out;

    cudaFuncSetAttribute(gram_mma, cudaFuncAttributeMaxDynamicSharedMemorySize, MM_SMEM);
    cudaFuncSetAttribute(final_mma, cudaFuncAttributeMaxDynamicSharedMemorySize, MM_SMEM);
    cudaFuncSetAttribute(gemm_tc<0>, cudaFuncAttributeMaxDynamicSharedMemorySize, MM_SMEM);
    cudaFuncSetAttribute(gemm_tc<1>, cudaFuncAttributeMaxDynamicSharedMemorySize, MM_SMEM);

    convert_x<<<NB * NC * NS / (256 * 8), 256>>>(x);
    convert_xt<<<dim3(64, 4, NB), 256>>>(x);
    gram_mma<<<dim3(4, 2, NB), NT, MM_SMEM>>>();
    reduce_g_kernel<<<NB * NC * NC / 4 / 256, 256>>>();
    gemm_tc<0><<<dim3(2, 4, NB), NT, MM_SMEM>>>(w_qkv);
    attn_kernel<<<dim3(NHEADS, NB), 256>>>(w_qkv);
    gemm_tc<1><<<dim3(2, 2, NB), NT, MM_SMEM>>>(w_out);
    final_mma<<<dim3(32, 2, NB), NT, MM_SMEM>>>(b_out, out);
}

// round 12
// speedup vs baseline: 1.7970x; 1.0539x over previous
#include <cuda_runtime.h>
#include <cuda_bf16.h>

#define NB 16
#define NC 256
#define NS 4096
#define NH 512
#define NHEADS 8

typedef unsigned long long u64;
typedef unsigned int u32;
typedef unsigned short u16;

// ---------------- scratch (static device memory, 16B-aligned) ----------------
__device__ __align__(16) float g_Gpart[2][NB][NC][NC];       // 8 MB
__device__ __align__(16) float g_G[NB][NC][NC];              // 4 MB
__device__ __align__(16) float g_QG[NB][NH][NC];             // 8 MB
__device__ __align__(16) float g_M[NB][NH][NC];              // 8 MB
__device__ __align__(16) __nv_bfloat16 g_Phi[NB][NC][NC];    // 2 MB  P hi
__device__ __align__(16) __nv_bfloat16 g_Plo[NB][NC][NC];    // 2 MB  P lo
__device__ __align__(16) __nv_bfloat16 g_XThi[NB][NS][NC];   // 32 MB X^T hi
__device__ __align__(16) __nv_bfloat16 g_XTlo[NB][NS][NC];   // 32 MB X^T lo
__device__ __align__(16) __nv_bfloat16 g_Xhi[NB][NC][NS];    // 32 MB X hi
__device__ __align__(16) __nv_bfloat16 g_Xlo[NB][NC][NS];    // 32 MB X lo

// ---------------- helpers ----------------------------------------------------
__device__ __forceinline__ u32 smem_u32(const void* p) {
    u32 a;
    asm("{ .reg .u64 t; cvta.to.shared.u64 t, %1; cvt.u32.u64 %0, t; }" : "=r"(a) : "l"(p));
    return a;
}
__device__ __forceinline__ void split4(float4 v, u64& hv, u64& lv) {
    __nv_bfloat16 h0 = __float2bfloat16(v.x), h1 = __float2bfloat16(v.y);
    __nv_bfloat16 h2 = __float2bfloat16(v.z), h3 = __float2bfloat16(v.w);
    __nv_bfloat16 l0 = __float2bfloat16(v.x - __bfloat162float(h0));
    __nv_bfloat16 l1 = __float2bfloat16(v.y - __bfloat162float(h1));
    __nv_bfloat16 l2 = __float2bfloat16(v.z - __bfloat162float(h2));
    __nv_bfloat16 l3 = __float2bfloat16(v.w - __bfloat162float(h3));
    hv = (u64)__bfloat16_as_ushort(h0) | ((u64)__bfloat16_as_ushort(h1) << 16) |
         ((u64)__bfloat16_as_ushort(h2) << 32) | ((u64)__bfloat16_as_ushort(h3) << 48);
    lv = (u64)__bfloat16_as_ushort(l0) | ((u64)__bfloat16_as_ushort(l1) << 16) |
         ((u64)__bfloat16_as_ushort(l2) << 32) | ((u64)__bfloat16_as_ushort(l3) << 48);
}
__device__ __forceinline__ void split1(float v, __nv_bfloat16& h, __nv_bfloat16& l) {
    h = __float2bfloat16(v);
    l = __float2bfloat16(v - __bfloat162float(h));
}
__device__ __forceinline__ void split2_u32(float a, float b, u32& hw, u32& lw) {
    __nv_bfloat16 ha, la, hb, lb;
    split1(a, ha, la);
    split1(b, hb, lb);
    hw = (u32)__bfloat16_as_ushort(ha) | ((u32)__bfloat16_as_ushort(hb) << 16);
    lw = (u32)__bfloat16_as_ushort(la) | ((u32)__bfloat16_as_ushort(lb) << 16);
}
__device__ __forceinline__ void ldsm4(u32* r, u32 addr) {
    asm volatile("ldmatrix.sync.aligned.m8n8.x4.shared.b16 {%0,%1,%2,%3}, [%4];"
                 : "=r"(r[0]), "=r"(r[1]), "=r"(r[2]), "=r"(r[3]) : "r"(addr));
}
__device__ __forceinline__ void mma_bf16(float* d, const u32* a, const u32* b) {
    asm volatile("mma.sync.aligned.m16n8k16.row.col.f32.bf16.bf16.f32 "
        "{%0,%1,%2,%3}, {%4,%5,%6,%7}, {%8,%9}, {%0,%1,%2,%3};"
        : "+f"(d[0]), "+f"(d[1]), "+f"(d[2]), "+f"(d[3])
        : "r"(a[0]), "r"(a[1]), "r"(a[2]), "r"(a[3]), "r"(b[0]), "r"(b[1]));
}
#define CP16(dst, src) asm volatile("cp.async.cg.shared.global [%0], [%1], 16;" :: "r"(dst), "l"(src))
#define CP_COMMIT()    asm volatile("cp.async.commit_group;" ::: "memory")
#define CP_WAIT1()     asm volatile("cp.async.wait_group 1;" ::: "memory")
#define CP_WAIT0()     asm volatile("cp.async.wait_group 0;" ::: "memory")

#define LDW 72                       // bf16/row (144 B = 9*16)
#define TILE_B (128 * LDW * 2)       // tile bytes (18432)
#define STG_B (4 * TILE_B)           // stage bytes (73728)
#define PIPE_SMEM (2 * STG_B)        // 147456
#define MM_SMEM STG_B                // single-stage kernels
#define NT 512

// =============================================================================
// convert_x: X fp32 -> Xhi/Xlo bf16 [b][c][ns]. grid 8192 x 256.
// =============================================================================
__global__ __launch_bounds__(256) void convert_x(const float* __restrict__ x) {
    size_t i = ((size_t)blockIdx.x * 256 + threadIdx.x) * 8;
    float4 v0 = *(const float4*)(x + i);
    float4 v1 = *(const float4*)(x + i + 4);
    u64 h0, l0, h1, l1;
    split4(v0, h0, l0);
    split4(v1, h1, l1);
    *(ulonglong2*)((__nv_bfloat16*)g_Xhi + i) = make_ulonglong2(h0, h1);
    *(ulonglong2*)((__nv_bfloat16*)g_Xlo + i) = make_ulonglong2(l0, l1);
}

// =============================================================================
// gram_mma: cp.async double-buffered. grid (4,2,NB), 512 thr, 144KB smem.
// =============================================================================
__global__ __launch_bounds__(NT) void gram_mma() {
    extern __shared__ __align__(16) char sm[];
    const u32 smb = smem_u32(sm);

    const int bi = blockIdx.x >> 1, bj = blockIdx.x & 1;
    const int s = blockIdx.y, b = blockIdx.z;
    const int tid = threadIdx.x, lane = tid & 31, wid = tid >> 5;
    const int wm = wid >> 2, wn = wid & 3;
    const bool diag = (bi == bj);

    const int g = lane >> 3, r8 = lane & 7;
    const int offA = (r8 + (g & 1) * 8) * LDW + (g >> 1) * 8;
    const int offB = (r8 + (g >> 1) * 8) * LDW + (g & 1) * 8;

    const int fr = tid >> 2, fs = (tid & 3) * 32;   // fill: 4 thr/row, 32B each x2

    float acc[2][4][4] = {};
    const int NCH = 32;

#define GRAM_FILL(st, c) do {                                                       \
    const int _k0 = s * 2048 + (c) * 64;                                            \
    const u32 _sb = smb + (st) * STG_B;                                             \
    const char* _ah = (const char*)&g_Xhi[b][bi * 128 + fr][_k0] + fs;              \
    const char* _al = (const char*)&g_Xlo[b][bi * 128 + fr][_k0] + fs;              \
    u32 _dA = _sb + fr * 144 + fs;                                                  \
    CP16(_dA, _ah); CP16(_dA + 16, _ah + 16);                                       \
    CP16(_dA + TILE_B, _al); CP16(_dA + TILE_B + 16, _al + 16);                     \
    if (!diag) {                                                                    \
        const char* _bh = (const char*)&g_Xhi[b][bj * 128 + fr][_k0] + fs;          \
        const char* _bl = (const char*)&g_Xlo[b][bj * 128 + fr][_k0] + fs;          \
        u32 _dB = _sb + 2 * TILE_B + fr * 144 + fs;                                 \
        CP16(_dB, _bh); CP16(_dB + 16, _bh + 16);                                   \
        CP16(_dB + TILE_B, _bl); CP16(_dB + TILE_B + 16, _bl + 16);                 \
    }                                                                               \
    CP_COMMIT();                                                                    \
} while (0)

    GRAM_FILL(0, 0);
    for (int c = 0; c < NCH; c++) {
        const int st = c & 1;
        if (c + 1 < NCH) { GRAM_FILL(st ^ 1, c + 1); CP_WAIT1(); }
        else CP_WAIT0();
        __syncthreads();
        const u32 aHb = smb + st * STG_B;
        const u32 aLb = aHb + TILE_B;
        const u32 bHb = diag ? aHb : aHb + 2 * TILE_B;
        const u32 bLb = diag ? aLb : aHb + 3 * TILE_B;
#pragma unroll
        for (int ks = 0; ks < 4; ks++) {
            u32 ah[2][4], al[2][4], bh[2][4], bl[2][4];
#pragma unroll
            for (int mf = 0; mf < 2; mf++) {
                u32 o = 2u * (u32)(offA + (wm * 32 + mf * 16) * LDW + ks * 16);
                ldsm4(ah[mf], aHb + o);
                ldsm4(al[mf], aLb + o);
            }
#pragma unroll
            for (int p = 0; p < 2; p++) {
                u32 o = 2u * (u32)(offB + (wn * 32 + p * 16) * LDW + ks * 16);
                ldsm4(bh[p], bHb + o);
                ldsm4(bl[p], bLb + o);
            }
#pragma unroll
            for (int mf = 0; mf < 2; mf++)
#pragma unroll
                for (int p = 0; p < 2; p++)
#pragma unroll
                    for (int hh = 0; hh < 2; hh++) {
                        int nb = p * 2 + hh;
                        mma_bf16(acc[mf][nb], ah[mf], &bh[p][hh * 2]);
                        mma_bf16(acc[mf][nb], ah[mf], &bl[p][hh * 2]);
                        mma_bf16(acc[mf][nb], al[mf], &bh[p][hh * 2]);
                    }
        }
        __syncthreads();
    }

    float* Gp = &g_Gpart[s][b][0][0];
    const int re = bi * 128 + wm * 32 + (lane >> 2);
    const int ce = bj * 128 + wn * 32 + 2 * (lane & 3);
#pragma unroll
    for (int mf = 0; mf < 2; mf++)
#pragma unroll
        for (int nb = 0; nb < 4; nb++) {
            int rr = re + mf * 16, cc = ce + nb * 8;
            float2 v0; v0.x = acc[mf][nb][0]; v0.y = acc[mf][nb][1];
            float2 v1; v1.x = acc[mf][nb][2]; v1.y = acc[mf][nb][3];
            *(float2*)&Gp[(size_t)rr * NC + cc] = v0;
            *(float2*)&Gp[(size_t)(rr + 8) * NC + cc] = v1;
        }
}

// =============================================================================
// convert_xt: X fp32 -> XT hi/lo [b][ns][c]. grid (64,4,NB), 256 thr.
// =============================================================================
__global__ __launch_bounds__(256) void convert_xt(const float* __restrict__ x) {
    __shared__ __align__(16) float T[64][68];
    const int ns0 = blockIdx.x * 64, c0 = blockIdx.y * 64, b = blockIdx.z;
    const int tid = threadIdx.x;
    {
        int r = tid >> 2, j = tid & 3;
        const float* src = x + ((size_t)b * NC + c0 + r) * NS + ns0 + j * 16;
        *(float4*)&T[r][j * 16 + 0] = *(const float4*)(src + 0);
        *(float4*)&T[r][j * 16 + 4] = *(const float4*)(src + 4);
        *(float4*)&T[r][j * 16 + 8] = *(const float4*)(src + 8);
        *(float4*)&T[r][j * 16 + 12] = *(const float4*)(src + 12);
    }
    __syncthreads();
    {
        int rn = tid >> 2, j = tid & 3;
        u32 hw[8], lw[8];
#pragma unroll
        for (int kk = 0; kk < 8; kk++)
            split2_u32(T[j * 16 + 2 * kk][rn], T[j * 16 + 2 * kk + 1][rn], hw[kk], lw[kk]);
        uint4* dh = (uint4*)&g_XThi[b][ns0 + rn][c0 + j * 16];
        uint4* dl = (uint4*)&g_XTlo[b][ns0 + rn][c0 + j * 16];
        dh[0] = make_uint4(hw[0], hw[1], hw[2], hw[3]);
        dh[1] = make_uint4(hw[4], hw[5], hw[6], hw[7]);
        dl[0] = make_uint4(lw[0], lw[1], lw[2], lw[3]);
        dl[1] = make_uint4(lw[4], lw[5], lw[6], lw[7]);
    }
}

// =============================================================================
// reduce: G = Gpart[0] + Gpart[1]
// =============================================================================
__global__ __launch_bounds__(256) void reduce_g_kernel() {
    int i = blockIdx.x * 256 + threadIdx.x;
    const float4* p = (const float4*)g_Gpart;
    const int stride = NB * NC * NC / 4;
    float4 a = p[i], c = p[stride + i];
    a.x += c.x; a.y += c.y; a.z += c.z; a.w += c.w;
    ((float4*)g_G)[i] = a;
}

// =============================================================================
// gemm_tc: 3-term-split tensor GEMM, 512 threads, 32x32 warp tiles.
// MODE 0: QG = Wq * G (K=256), grid (2,4,NB). C -> g_QG fp32.
// MODE 1: P = W_out * M (K=512), grid (2,2,NB). C -> g_Phi/g_Plo bf16 split.
// =============================================================================
template <int MODE>
__global__ __launch_bounds__(NT) void gemm_tc(const float* __restrict__ W) {
    extern __shared__ __align__(16) char smc[];
    __nv_bfloat16* sm = (__nv_bfloat16*)smc;
    __nv_bfloat16* Ah = sm;
    __nv_bfloat16* Al = sm + 128 * LDW;
    __nv_bfloat16* Bh = sm + 2 * 128 * LDW;
    __nv_bfloat16* Bl = sm + 3 * 128 * LDW;

    constexpr int K = (MODE == 0) ? 256 : 512;
    const int nt = blockIdx.x, mt = blockIdx.y, b = blockIdx.z;
    const int tid = threadIdx.x, lane = tid & 31, wid = tid >> 5;
    const int wm = wid >> 2, wn = wid & 3;

    const u32 aHb = smem_u32(Ah), aLb = smem_u32(Al);
    const u32 bHb = smem_u32(Bh), bLb = smem_u32(Bl);
    const int g = lane >> 3, r8 = lane & 7;
    const int offA = (r8 + (g & 1) * 8) * LDW + (g >> 1) * 8;
    const int offB = (r8 + (g >> 1) * 8) * LDW + (g & 1) * 8;

    const float* Ab = W + (size_t)(mt * 128) * K;
    const float* Bb = (MODE == 0) ? &g_G[b][0][0] : &g_M[b][0][0];

    float acc[2][4][4] = {};

    for (int c = 0; c < K / 64; c++) {
        const int k0 = c * 64;
        {
            const int r = tid >> 2, sg = tid & 3;
            const float* src = Ab + (size_t)r * K + k0 + sg * 16;
#pragma unroll
            for (int j = 0; j < 4; j++) {
                float4 v = ((const float4*)src)[j];
                u64 hv, lv; split4(v, hv, lv);
                *(u64*)&Ah[r * LDW + sg * 16 + j * 4] = hv;
                *(u64*)&Al[r * LDW + sg * 16 + j * 4] = lv;
            }
        }
        if (MODE == 0) {
            const int r = tid >> 2, sg = tid & 3;
            const float* src = Bb + (size_t)(nt * 128 + r) * K + k0 + sg * 16;
#pragma unroll
            for (int j = 0; j < 4; j++) {
                float4 v = ((const float4*)src)[j];
                u64 hv, lv; split4(v, hv, lv);
                *(u64*)&Bh[r * LDW + sg * 16 + j * 4] = hv;
                *(u64*)&Bl[r * LDW + sg * 16 + j * 4] = lv;
            }
        } else {
            const int kl = tid >> 3, ns8 = tid & 7;
            const float* src = Bb + (size_t)(k0 + kl) * NC + nt * 128 + ns8 * 16;
#pragma unroll
            for (int j = 0; j < 4; j++) {
                float4 v = ((const float4*)src)[j];
                int n = ns8 * 16 + j * 4;
                __nv_bfloat16 h, l;
                split1(v.x, h, l); Bh[(n + 0) * LDW + kl] = h; Bl[(n + 0) * LDW + kl] = l;
                split1(v.y, h, l); Bh[(n + 1) * LDW + kl] = h; Bl[(n + 1) * LDW + kl] = l;
                split1(v.z, h, l); Bh[(n + 2) * LDW + kl] = h; Bl[(n + 2) * LDW + kl] = l;
                split1(v.w, h, l); Bh[(n + 3) * LDW + kl] = h; Bl[(n + 3) * LDW + kl] = l;
            }
        }
        __syncthreads();
#pragma unroll
        for (int ks = 0; ks < 4; ks++) {
            u32 ah[2][4], al[2][4], bh[2][4], bl[2][4];
#pragma unroll
            for (int mf = 0; mf < 2; mf++) {
                u32 o = 2u * (u32)(offA + (wm * 32 + mf * 16) * LDW + ks * 16);
                ldsm4(ah[mf], aHb + o);
                ldsm4(al[mf], aLb + o);
            }
#pragma unroll
            for (int p = 0; p < 2; p++) {
                u32 o = 2u * (u32)(offB + (wn * 32 + p * 16) * LDW + ks * 16);
                ldsm4(bh[p], bHb + o);
                ldsm4(bl[p], bLb + o);
            }
#pragma unroll
            for (int mf = 0; mf < 2; mf++)
#pragma unroll
                for (int p = 0; p < 2; p++)
#pragma unroll
                    for (int hh = 0; hh < 2; hh++) {
                        int nb = p * 2 + hh;
                        mma_bf16(acc[mf][nb], ah[mf], &bh[p][hh * 2]);
                        mma_bf16(acc[mf][nb], ah[mf], &bl[p][hh * 2]);
                        mma_bf16(acc[mf][nb], al[mf], &bh[p][hh * 2]);
                    }
        }
        __syncthreads();
    }

    const int mB = mt * 128 + wm * 32 + (lane >> 2);
    const int nB = nt * 128 + wn * 32 + 2 * (lane & 3);
#pragma unroll
    for (int mf = 0; mf < 2; mf++) {
        int r = mB + mf * 16;
#pragma unroll
        for (int nb = 0; nb < 4; nb++) {
            int cc = nB + nb * 8;
            if (MODE == 0) {
                float* Cb = &g_QG[b][0][0];
                float2 v0; v0.x = acc[mf][nb][0]; v0.y = acc[mf][nb][1];
                float2 v1; v1.x = acc[mf][nb][2]; v1.y = acc[mf][nb][3];
                *(float2*)&Cb[(size_t)r * NC + cc] = v0;
                *(float2*)&Cb[(size_t)(r + 8) * NC + cc] = v1;
            } else {
                u32 hw, lw;
                split2_u32(acc[mf][nb][0], acc[mf][nb][1], hw, lw);
                *(u32*)&g_Phi[b][r][cc] = hw;
                *(u32*)&g_Plo[b][r][cc] = lw;
                split2_u32(acc[mf][nb][2], acc[mf][nb][3], hw, lw);
                *(u32*)&g_Phi[b][r + 8][cc] = hw;
                *(u32*)&g_Plo[b][r + 8][cc] = lw;
            }
        }
    }
}

// =============================================================================
// attn: per-(batch,head) sim -> softmax -> M = attn*Wv  (unchanged)
// =============================================================================
__global__ __launch_bounds__(256) void attn_kernel(const float* __restrict__ wqkv) {
    const int h = blockIdx.x, b = blockIdx.y;
    __shared__ float S[64][65];
    __shared__ __align__(16) float Buf[4160];
    const int tid = threadIdx.x, tx = tid & 15, ty = tid >> 4;

    const float* QGb = &g_QG[b][h * 64][0];
    const float* Wk = wqkv + (size_t)(NH + h * 64) * NC;
    const float* Wv = wqkv + (size_t)(2 * NH + h * 64) * NC;
    float* Qs = Buf;
    float* Ks = Buf + 64 * 32;

    float acc[4][4] = {};
    for (int kc = 0; kc < NC; kc += 32) {
#pragma unroll
        for (int it = 0; it < 2; it++) {
            int idx = it * 256 + tid;
            int row = idx >> 3, c4 = idx & 7;
            *(float4*)&Qs[row * 32 + c4 * 4] = *(const float4*)(QGb + (size_t)row * NC + kc + c4 * 4);
            float4 v = *(const float4*)(Wk + (size_t)row * NC + kc + c4 * 4);
            Ks[(c4 * 4 + 0) * 65 + row] = v.x;
            Ks[(c4 * 4 + 1) * 65 + row] = v.y;
            Ks[(c4 * 4 + 2) * 65 + row] = v.z;
            Ks[(c4 * 4 + 3) * 65 + row] = v.w;
        }
        __syncthreads();
#pragma unroll
        for (int kk = 0; kk < 32; kk++) {
            float a[4], bb[4];
#pragma unroll
            for (int i = 0; i < 4; i++) a[i] = Qs[(ty + 16 * i) * 32 + kk];
#pragma unroll
            for (int j = 0; j < 4; j++) bb[j] = Ks[kk * 65 + tx + 16 * j];
#pragma unroll
            for (int i = 0; i < 4; i++)
#pragma unroll
                for (int j = 0; j < 4; j++) acc[i][j] += a[i] * bb[j];
        }
        __syncthreads();
    }
    const float scale = 0.125f;
#pragma unroll
    for (int i = 0; i < 4; i++)
#pragma unroll
        for (int j = 0; j < 4; j++)
            S[ty + 16 * i][tx + 16 * j] = acc[i][j] * scale;
    __syncthreads();

    if (tid < 64) {
        float m = -1e30f;
        for (int j = 0; j < 64; j++) m = fmaxf(m, S[tid][j]);
        float sum = 0.f;
        for (int j = 0; j < 64; j++) {
            float e = expf(S[tid][j] - m);
            S[tid][j] = e; sum += e;
        }
        float inv = 1.f / sum;
        for (int j = 0; j < 64; j++) S[tid][j] *= inv;
    }
    __syncthreads();

    float* Ms = &g_M[b][h * 64][0];
    float* Vs = Buf;
    for (int cc = 0; cc < NC; cc += 64) {
#pragma unroll
        for (int it = 0; it < 4; it++) {
            int idx = it * 256 + tid;
            int row = idx >> 4, c4 = idx & 15;
            *(float4*)&Vs[row * 64 + c4 * 4] = *(const float4*)(Wv + (size_t)row * NC + cc + c4 * 4);
        }
        __syncthreads();
        float o[4][4] = {};
        for (int j = 0; j < 64; j++) {
            float a[4], vv[4];
#pragma unroll
            for (int i = 0; i < 4; i++) a[i] = S[ty + 16 * i][j];
#pragma unroll
            for (int jj = 0; jj < 4; jj++) vv[jj] = Vs[j * 64 + tx + 16 * jj];
#pragma unroll
            for (int i = 0; i < 4; i++)
#pragma unroll
                for (int jj = 0; jj < 4; jj++) o[i][jj] += a[i] * vv[jj];
        }
#pragma unroll
        for (int i = 0; i < 4; i++)
#pragma unroll
            for (int jj = 0; jj < 4; jj++)
                Ms[(size_t)(ty + 16 * i) * NC + cc + tx + 16 * jj] = o[i][jj];
        __syncthreads();
    }
}

// =============================================================================
// final_mma: out = P*X + bias. cp.async double-buffered, all fills pure copies.
// grid (32,2,NB), 512 threads, 144KB smem, NCH=4.
// =============================================================================
__global__ __launch_bounds__(NT) void final_mma(const float* __restrict__ bias,
                                                float* __restrict__ out) {
    extern __shared__ __align__(16) char sm[];
    const u32 smb = smem_u32(sm);

    const int nt = blockIdx.x, mt = blockIdx.y, b = blockIdx.z;
    const int tid = threadIdx.x, lane = tid & 31, wid = tid >> 5;
    const int wm = wid >> 2, wn = wid & 3;

    const int g = lane >> 3, r8 = lane & 7;
    const int offA = (r8 + (g & 1) * 8) * LDW + (g >> 1) * 8;
    const int offB = (r8 + (g >> 1) * 8) * LDW + (g & 1) * 8;

    const int fr = tid >> 2, fs = (tid & 3) * 32;

    float acc[2][4][4] = {};
    const int NCH = 4;

#define FIN_FILL(st, c) do {                                                        \
    const int _k0 = (c) * 64;                                                       \
    const u32 _sb = smb + (st) * STG_B;                                             \
    const char* _ah = (const char*)&g_Phi[b][mt * 128 + fr][_k0] + fs;              \
    const char* _al = (const char*)&g_Plo[b][mt * 128 + fr][_k0] + fs;              \
    u32 _dA = _sb + fr * 144 + fs;                                                  \
    CP16(_dA, _ah); CP16(_dA + 16, _ah + 16);                                       \
    CP16(_dA + TILE_B, _al); CP16(_dA + TILE_B + 16, _al + 16);                     \
    const char* _bh = (const char*)&g_XThi[b][nt * 128 + fr][_k0] + fs;             \
    const char* _bl = (const char*)&g_XTlo[b][nt * 128 + fr][_k0] + fs;             \
    u32 _dB = _sb + 2 * TILE_B + fr * 144 + fs;                                     \
    CP16(_dB, _bh); CP16(_dB + 16, _bh + 16);                                       \
    CP16(_dB + TILE_B, _bl); CP16(_dB + TILE_B + 16, _bl + 16);                     \
    CP_COMMIT();                                                                    \
} while (0)

    FIN_FILL(0, 0);
    for (int c = 0; c < NCH; c++) {
        const int st = c & 1;
        if (c + 1 < NCH) { FIN_FILL(st ^ 1, c + 1); CP_WAIT1(); }
        else CP_WAIT0();
        __syncthreads();
        const u32 aHb = smb + st * STG_B;
        const u32 aLb = aHb + TILE_B;
        const u32 bHb = aHb + 2 * TILE_B;
        const u32 bLb = aHb + 3 * TILE_B;
#pragma unroll
        for (int ks = 0; ks < 4; ks++) {
            u32 ah[2][4], al[2][4], bh[2][4], bl[2][4];
#pragma unroll
            for (int mf = 0; mf < 2; mf++) {
                u32 o = 2u * (u32)(offA + (wm * 32 + mf * 16) * LDW + ks * 16);
                ldsm4(ah[mf], aHb + o);
                ldsm4(al[mf], aLb + o);
            }
#pragma unroll
            for (int p = 0; p < 2; p++) {
                u32 o = 2u * (u32)(offB + (wn * 32 + p * 16) * LDW + ks * 16);
                ldsm4(bh[p], bHb + o);
                ldsm4(bl[p], bLb + o);
            }
#pragma unroll
            for (int mf = 0; mf < 2; mf++)
#pragma unroll
                for (int p = 0; p < 2; p++)
#pragma unroll
                    for (int hh = 0; hh < 2; hh++) {
                        int nb = p * 2 + hh;
                        mma_bf16(acc[mf][nb], ah[mf], &bh[p][hh * 2]);
                        mma_bf16(acc[mf][nb], ah[mf], &bl[p][hh * 2]);
                        mma_bf16(acc[mf][nb], al[mf], &bh[p][hh * 2]);
                    }
        }
        __syncthreads();
    }

    const int coB = mt * 128 + wm * 32 + (lane >> 2);
    const int nsB = nt * 128 + wn * 32 + 2 * (lane & 3);
#pragma unroll
    for (int mf = 0; mf < 2; mf++) {
        int co = coB + mf * 16;
        float bv0 = bias[co], bv1 = bias[co + 8];
        float* row0 = out + ((size_t)b * NC + co) * NS;
        float* row1 = out + ((size_t)b * NC + co + 8) * NS;
#pragma unroll
        for (int nb = 0; nb < 4; nb++) {
            int cc = nsB + nb * 8;
            float2 v0; v0.x = acc[mf][nb][0] + bv0; v0.y = acc[mf][nb][1] + bv0;
            float2 v1; v1.x = acc[mf][nb][2] + bv1; v1.y = acc[mf][nb][3] + bv1;
            *(float2*)&row0[cc] = v0;
            *(float2*)&row1[cc] = v1;
        }
    }
}

// =============================================================================
extern "C" void kernel_launch(void* const* d_in, const int* in_sizes, int n_in,
                              void* d_out, int out_size) {
    (void)in_sizes; (void)n_in; (void)out_size;
    const float* x     = (const float*)d_in[0];
    const float* w_qkv = (const float*)d_in[1];
    const float* w_out = (const float*)d_in[2];
    const float* b_out = (const float*)d_in[3];
    float* out = (float*)d_out;

    cudaFuncSetAttribute(gram_mma, cudaFuncAttributeMaxDynamicSharedMemorySize, PIPE_SMEM);
    cudaFuncSetAttribute(final_mma, cudaFuncAttributeMaxDynamicSharedMemorySize, PIPE_SMEM);
    cudaFuncSetAttribute(gemm_tc<0>, cudaFuncAttributeMaxDynamicSharedMemorySize, MM_SMEM);
    cudaFuncSetAttribute(gemm_tc<1>, cudaFuncAttributeMaxDynamicSharedMemorySize, MM_SMEM);

    convert_x<<<NB * NC * NS / (256 * 8), 256>>>(x);
    convert_xt<<<dim3(64, 4, NB), 256>>>(x);
    gram_mma<<<dim3(4, 2, NB), NT, PIPE_SMEM>>>();
    reduce_g_kernel<<<NB * NC * NC / 4 / 256, 256>>>();
    gemm_tc<0><<<dim3(2, 4, NB), NT, MM_SMEM>>>(w_qkv);
    attn_kernel<<<dim3(NHEADS, NB), 256>>>(w_qkv);
    gemm_tc<1><<<dim3(2, 2, NB), NT, MM_SMEM>>>(w_out);
    final_mma<<<dim3(32, 2, NB), NT, PIPE_SMEM>>>(b_out, out);
}

// round 13
// speedup vs baseline: 2.1133x; 1.1761x over previous
#include <cuda_runtime.h>
#include <cuda_bf16.h>

#define NB 16
#define NC 256
#define NS 4096
#define NH 512
#define NHEADS 8

typedef unsigned long long u64;
typedef unsigned int u32;
typedef unsigned short u16;

// ---------------- scratch (static device memory, 16B-aligned) ----------------
__device__ __align__(16) float g_Gpart[2][NB][NC][NC];       // 8 MB
__device__ __align__(16) float g_QG[NB][NH][NC];             // 8 MB
__device__ __align__(16) __nv_bfloat16 g_Ghi[NB][NC][NC];    // 2 MB
__device__ __align__(16) __nv_bfloat16 g_Glo[NB][NC][NC];    // 2 MB
__device__ __align__(16) __nv_bfloat16 g_Mhi[NB][NH][NC];    // 4 MB
__device__ __align__(16) __nv_bfloat16 g_Mlo[NB][NH][NC];    // 4 MB
__device__ __align__(16) __nv_bfloat16 g_Phi[NB][NC][NC];    // 2 MB
__device__ __align__(16) __nv_bfloat16 g_Plo[NB][NC][NC];    // 2 MB
__device__ __align__(16) __nv_bfloat16 g_Xhi[NB][NC][NS];    // 32 MB
__device__ __align__(16) __nv_bfloat16 g_Xlo[NB][NC][NS];    // 32 MB
__device__ __align__(16) __nv_bfloat16 g_Wqhi[NH * NC], g_Wqlo[NH * NC];       // 256 KB x2
__device__ __align__(16) __nv_bfloat16 g_Wouthi[NC * NH], g_Woutlo[NC * NH];   // 256 KB x2

// ---------------- helpers ----------------------------------------------------
__device__ __forceinline__ u32 smem_u32(const void* p) {
    u32 a;
    asm("{ .reg .u64 t; cvta.to.shared.u64 t, %1; cvt.u32.u64 %0, t; }" : "=r"(a) : "l"(p));
    return a;
}
__device__ __forceinline__ void split4(float4 v, u64& hv, u64& lv) {
    __nv_bfloat16 h0 = __float2bfloat16(v.x), h1 = __float2bfloat16(v.y);
    __nv_bfloat16 h2 = __float2bfloat16(v.z), h3 = __float2bfloat16(v.w);
    __nv_bfloat16 l0 = __float2bfloat16(v.x - __bfloat162float(h0));
    __nv_bfloat16 l1 = __float2bfloat16(v.y - __bfloat162float(h1));
    __nv_bfloat16 l2 = __float2bfloat16(v.z - __bfloat162float(h2));
    __nv_bfloat16 l3 = __float2bfloat16(v.w - __bfloat162float(h3));
    hv = (u64)__bfloat16_as_ushort(h0) | ((u64)__bfloat16_as_ushort(h1) << 16) |
         ((u64)__bfloat16_as_ushort(h2) << 32) | ((u64)__bfloat16_as_ushort(h3) << 48);
    lv = (u64)__bfloat16_as_ushort(l0) | ((u64)__bfloat16_as_ushort(l1) << 16) |
         ((u64)__bfloat16_as_ushort(l2) << 32) | ((u64)__bfloat16_as_ushort(l3) << 48);
}
__device__ __forceinline__ void split1(float v, __nv_bfloat16& h, __nv_bfloat16& l) {
    h = __float2bfloat16(v);
    l = __float2bfloat16(v - __bfloat162float(h));
}
__device__ __forceinline__ void split2_u32(float a, float b, u32& hw, u32& lw) {
    __nv_bfloat16 ha, la, hb, lb;
    split1(a, ha, la);
    split1(b, hb, lb);
    hw = (u32)__bfloat16_as_ushort(ha) | ((u32)__bfloat16_as_ushort(hb) << 16);
    lw = (u32)__bfloat16_as_ushort(la) | ((u32)__bfloat16_as_ushort(lb) << 16);
}
__device__ __forceinline__ void ldsm4(u32* r, u32 addr) {
    asm volatile("ldmatrix.sync.aligned.m8n8.x4.shared.b16 {%0,%1,%2,%3}, [%4];"
                 : "=r"(r[0]), "=r"(r[1]), "=r"(r[2]), "=r"(r[3]) : "r"(addr));
}
__device__ __forceinline__ void ldsm4t(u32* r, u32 addr) {
    asm volatile("ldmatrix.sync.aligned.m8n8.x4.trans.shared.b16 {%0,%1,%2,%3}, [%4];"
                 : "=r"(r[0]), "=r"(r[1]), "=r"(r[2]), "=r"(r[3]) : "r"(addr));
}
__device__ __forceinline__ void mma_bf16(float* d, const u32* a, const u32* b) {
    asm volatile("mma.sync.aligned.m16n8k16.row.col.f32.bf16.bf16.f32 "
        "{%0,%1,%2,%3}, {%4,%5,%6,%7}, {%8,%9}, {%0,%1,%2,%3};"
        : "+f"(d[0]), "+f"(d[1]), "+f"(d[2]), "+f"(d[3])
        : "r"(a[0]), "r"(a[1]), "r"(a[2]), "r"(a[3]), "r"(b[0]), "r"(b[1]));
}
#define CP16(dst, src) asm volatile("cp.async.cg.shared.global [%0], [%1], 16;" :: "r"(dst), "l"(src))
#define CP_COMMIT()    asm volatile("cp.async.commit_group;" ::: "memory")
#define CP_WAIT1()     asm volatile("cp.async.wait_group 1;" ::: "memory")
#define CP_WAIT0()     asm volatile("cp.async.wait_group 0;" ::: "memory")

#define LDW 72                        // nontrans row: 144 B
#define LDWB 136                      // trans row: 272 B
#define TA 18432                      // nontrans tile bytes (128 x 144)
#define TTB 17408                     // trans tile bytes (64 x 272)
#define STG_A (4 * TA)                // 73728 (gram, tc0)
#define STG_T (2 * TA + 2 * TTB)      // 71680 (tc1, final)
#define PIPE_A (2 * STG_A)            // 147456
#define PIPE_T (2 * STG_T)            // 143360
#define NT 512

// shared mma stage: A nontrans always; B nontrans (TB=0) or trans (TB=1)
template <bool TB>
__device__ __forceinline__ void mma_stage(u32 aHb, u32 aLb, u32 bHb, u32 bLb,
                                          int offA, int offBx, int wm, int wn,
                                          float acc[2][4][4]) {
#pragma unroll
    for (int ks = 0; ks < 4; ks++) {
        u32 ah[2][4], al[2][4], bh[2][4], bl[2][4];
#pragma unroll
        for (int mf = 0; mf < 2; mf++) {
            u32 o = 2u * (u32)(offA + (wm * 32 + mf * 16) * LDW + ks * 16);
            ldsm4(ah[mf], aHb + o);
            ldsm4(al[mf], aLb + o);
        }
#pragma unroll
        for (int p = 0; p < 2; p++) {
            if (TB) {
                u32 o = 2u * (u32)(offBx + ks * 16 * LDWB + wn * 32 + p * 16);
                ldsm4t(bh[p], bHb + o);
                ldsm4t(bl[p], bLb + o);
            } else {
                u32 o = 2u * (u32)(offBx + (wn * 32 + p * 16) * LDW + ks * 16);
                ldsm4(bh[p], bHb + o);
                ldsm4(bl[p], bLb + o);
            }
        }
#pragma unroll
        for (int mf = 0; mf < 2; mf++)
#pragma unroll
            for (int p = 0; p < 2; p++)
#pragma unroll
                for (int hh = 0; hh < 2; hh++) {
                    int nb = p * 2 + hh;
                    mma_bf16(acc[mf][nb], ah[mf], &bh[p][hh * 2]);
                    mma_bf16(acc[mf][nb], ah[mf], &bl[p][hh * 2]);
                    mma_bf16(acc[mf][nb], al[mf], &bh[p][hh * 2]);
                }
    }
}

// =============================================================================
// convert_x: X fp32 -> Xhi/Xlo bf16 [b][c][ns]. grid 8192 x 256.
// =============================================================================
__global__ __launch_bounds__(256) void convert_x(const float* __restrict__ x) {
    size_t i = ((size_t)blockIdx.x * 256 + threadIdx.x) * 8;
    float4 v0 = *(const float4*)(x + i);
    float4 v1 = *(const float4*)(x + i + 4);
    u64 h0, l0, h1, l1;
    split4(v0, h0, l0);
    split4(v1, h1, l1);
    *(ulonglong2*)((__nv_bfloat16*)g_Xhi + i) = make_ulonglong2(h0, h1);
    *(ulonglong2*)((__nv_bfloat16*)g_Xlo + i) = make_ulonglong2(l0, l1);
}

// =============================================================================
// convert_w: Wq (w_qkv rows 0..511) + W_out -> split bf16. grid 128 x 256.
// =============================================================================
__global__ __launch_bounds__(256) void convert_w(const float* __restrict__ wq,
                                                 const float* __restrict__ wo) {
    int i = (blockIdx.x * 256 + threadIdx.x) * 8;
    const int NQ = NH * NC;
    const float* src;
    __nv_bfloat16 *dh, *dl;
    if (i < NQ) { src = wq + i; dh = g_Wqhi + i; dl = g_Wqlo + i; }
    else { int o = i - NQ; src = wo + o; dh = g_Wouthi + o; dl = g_Woutlo + o; }
    float4 v0 = *(const float4*)src;
    float4 v1 = *(const float4*)(src + 4);
    u64 h0, l0, h1, l1;
    split4(v0, h0, l0);
    split4(v1, h1, l1);
    *(ulonglong2*)dh = make_ulonglong2(h0, h1);
    *(ulonglong2*)dl = make_ulonglong2(l0, l1);
}

// =============================================================================
// gram_mma: symmetric blocks only ((0,0),(0,1),(1,1)). grid (3,2,NB), 512 thr.
// =============================================================================
__global__ __launch_bounds__(NT) void gram_mma() {
    extern __shared__ __align__(16) char sm[];
    const u32 smb = smem_u32(sm);

    const int bx = blockIdx.x;
    const int bi = (bx == 2) ? 1 : 0;
    const int bj = (bx == 0) ? 0 : 1;
    const int s = blockIdx.y, b = blockIdx.z;
    const int tid = threadIdx.x, lane = tid & 31, wid = tid >> 5;
    const int wm = wid >> 2, wn = wid & 3;
    const bool diag = (bi == bj);

    const int g = lane >> 3, r8 = lane & 7;
    const int offA = (r8 + (g & 1) * 8) * LDW + (g >> 1) * 8;
    const int offB = (r8 + (g >> 1) * 8) * LDW + (g & 1) * 8;

    const int fr = tid >> 2, fs = (tid & 3) * 32;

    float acc[2][4][4] = {};
    const int NCH = 32;

#define GRAM_FILL(st, c) do {                                                       \
    const int _k0 = s * 2048 + (c) * 64;                                            \
    const u32 _sb = smb + (st) * STG_A;                                             \
    const char* _ah = (const char*)&g_Xhi[b][bi * 128 + fr][_k0] + fs;              \
    const char* _al = (const char*)&g_Xlo[b][bi * 128 + fr][_k0] + fs;              \
    u32 _dA = _sb + fr * 144 + fs;                                                  \
    CP16(_dA, _ah); CP16(_dA + 16, _ah + 16);                                       \
    CP16(_dA + TA, _al); CP16(_dA + TA + 16, _al + 16);                             \
    if (!diag) {                                                                    \
        const char* _bh = (const char*)&g_Xhi[b][bj * 128 + fr][_k0] + fs;          \
        const char* _bl = (const char*)&g_Xlo[b][bj * 128 + fr][_k0] + fs;          \
        u32 _dB = _sb + 2 * TA + fr * 144 + fs;                                     \
        CP16(_dB, _bh); CP16(_dB + 16, _bh + 16);                                   \
        CP16(_dB + TA, _bl); CP16(_dB + TA + 16, _bl + 16);                         \
    }                                                                               \
    CP_COMMIT();                                                                    \
} while (0)

    GRAM_FILL(0, 0);
    for (int c = 0; c < NCH; c++) {
        const int st = c & 1;
        if (c + 1 < NCH) { GRAM_FILL(st ^ 1, c + 1); CP_WAIT1(); }
        else CP_WAIT0();
        __syncthreads();
        const u32 aHb = smb + st * STG_A;
        const u32 aLb = aHb + TA;
        const u32 bHb = diag ? aHb : aHb + 2 * TA;
        const u32 bLb = diag ? aLb : aHb + 3 * TA;
        mma_stage<false>(aHb, aLb, bHb, bLb, offA, offB, wm, wn, acc);
        __syncthreads();
    }

    float* Gp = &g_Gpart[s][b][0][0];
    const int re = bi * 128 + wm * 32 + (lane >> 2);
    const int ce = bj * 128 + wn * 32 + 2 * (lane & 3);
#pragma unroll
    for (int mf = 0; mf < 2; mf++)
#pragma unroll
        for (int nb = 0; nb < 4; nb++) {
            int rr = re + mf * 16, cc = ce + nb * 8;
            float2 v0; v0.x = acc[mf][nb][0]; v0.y = acc[mf][nb][1];
            float2 v1; v1.x = acc[mf][nb][2]; v1.y = acc[mf][nb][3];
            *(float2*)&Gp[(size_t)rr * NC + cc] = v0;
            *(float2*)&Gp[(size_t)(rr + 8) * NC + cc] = v1;
        }
}

// =============================================================================
// reduce_split_g: G = Gpart[0]+Gpart[1], mirror block (1,0) from (0,1),
// output split Ghi/Glo. grid (16, NB), 256 thr (64x64 tiles).
// =============================================================================
__global__ __launch_bounds__(256) void reduce_split_g() {
    const int t = blockIdx.x, b = blockIdx.y;
    const int ti = t >> 2, tj = t & 3;
    const int tid = threadIdx.x;
    const float* P0 = &g_Gpart[0][b][0][0];
    const float* P1 = &g_Gpart[1][b][0][0];
    const int r = tid >> 2, j = tid & 3;
    const bool mirror = (ti >= 2 && tj < 2);

    if (!mirror) {
        int gr = ti * 64 + r, gc = tj * 64 + j * 16;
        u32 hw[8], lw[8];
#pragma unroll
        for (int q = 0; q < 4; q++) {
            float4 a = *(const float4*)(P0 + (size_t)gr * NC + gc + q * 4);
            float4 c = *(const float4*)(P1 + (size_t)gr * NC + gc + q * 4);
            a.x += c.x; a.y += c.y; a.z += c.z; a.w += c.w;
            split2_u32(a.x, a.y, hw[2 * q], lw[2 * q]);
            split2_u32(a.z, a.w, hw[2 * q + 1], lw[2 * q + 1]);
        }
        uint4* dh = (uint4*)&g_Ghi[b][gr][gc];
        uint4* dl = (uint4*)&g_Glo[b][gr][gc];
        dh[0] = make_uint4(hw[0], hw[1], hw[2], hw[3]);
        dh[1] = make_uint4(hw[4], hw[5], hw[6], hw[7]);
        dl[0] = make_uint4(lw[0], lw[1], lw[2], lw[3]);
        dl[1] = make_uint4(lw[4], lw[5], lw[6], lw[7]);
    } else {
        __shared__ __align__(16) float T[64][68];
        int sr = tj * 64 + r, sc = ti * 64 + j * 16;   // source in block (0,1)
#pragma unroll
        for (int q = 0; q < 4; q++) {
            float4 a = *(const float4*)(P0 + (size_t)sr * NC + sc + q * 4);
            float4 c = *(const float4*)(P1 + (size_t)sr * NC + sc + q * 4);
            a.x += c.x; a.y += c.y; a.z += c.z; a.w += c.w;
            *(float4*)&T[r][j * 16 + q * 4] = a;
        }
        __syncthreads();
        u32 hw[8], lw[8];
#pragma unroll
        for (int kk = 0; kk < 8; kk++)
            split2_u32(T[j * 16 + 2 * kk][r], T[j * 16 + 2 * kk + 1][r], hw[kk], lw[kk]);
        uint4* dh = (uint4*)&g_Ghi[b][ti * 64 + r][tj * 64 + j * 16];
        uint4* dl = (uint4*)&g_Glo[b][ti * 64 + r][tj * 64 + j * 16];
        dh[0] = make_uint4(hw[0], hw[1], hw[2], hw[3]);
        dh[1] = make_uint4(hw[4], hw[5], hw[6], hw[7]);
        dl[0] = make_uint4(lw[0], lw[1], lw[2], lw[3]);
        dl[1] = make_uint4(lw[4], lw[5], lw[6], lw[7]);
    }
}

// =============================================================================
// gemm_tc<0>: QG = Wq*G (K=256), all-copy fills (Wq split, G split, B=[n][k]
// via symmetry), pipelined. grid (2,4,NB). Output QG fp32.
// =============================================================================
__global__ __launch_bounds__(NT) void gemm_tc0() {
    extern __shared__ __align__(16) char sm[];
    const u32 smb = smem_u32(sm);
    const int nt = blockIdx.x, mt = blockIdx.y, b = blockIdx.z;
    const int tid = threadIdx.x, lane = tid & 31, wid = tid >> 5;
    const int wm = wid >> 2, wn = wid & 3;
    const int g = lane >> 3, r8 = lane & 7;
    const int offA = (r8 + (g & 1) * 8) * LDW + (g >> 1) * 8;
    const int offB = (r8 + (g >> 1) * 8) * LDW + (g & 1) * 8;
    const int fr = tid >> 2, fs = (tid & 3) * 32;

    float acc[2][4][4] = {};
    const int NCH = 4;

#define TC0_FILL(st, c) do {                                                        \
    const int _k0 = (c) * 64;                                                       \
    const u32 _sb = smb + (st) * STG_A;                                             \
    const char* _ah = (const char*)(g_Wqhi + (size_t)(mt * 128 + fr) * NC + _k0) + fs; \
    const char* _al = (const char*)(g_Wqlo + (size_t)(mt * 128 + fr) * NC + _k0) + fs; \
    u32 _dA = _sb + fr * 144 + fs;                                                  \
    CP16(_dA, _ah); CP16(_dA + 16, _ah + 16);                                       \
    CP16(_dA + TA, _al); CP16(_dA + TA + 16, _al + 16);                             \
    const char* _bh = (const char*)&g_Ghi[b][nt * 128 + fr][_k0] + fs;              \
    const char* _bl = (const char*)&g_Glo[b][nt * 128 + fr][_k0] + fs;              \
    u32 _dB = _sb + 2 * TA + fr * 144 + fs;                                         \
    CP16(_dB, _bh); CP16(_dB + 16, _bh + 16);                                       \
    CP16(_dB + TA, _bl); CP16(_dB + TA + 16, _bl + 16);                             \
    CP_COMMIT();                                                                    \
} while (0)

    TC0_FILL(0, 0);
    for (int c = 0; c < NCH; c++) {
        const int st = c & 1;
        if (c + 1 < NCH) { TC0_FILL(st ^ 1, c + 1); CP_WAIT1(); }
        else CP_WAIT0();
        __syncthreads();
        const u32 aHb = smb + st * STG_A;
        mma_stage<false>(aHb, aHb + TA, aHb + 2 * TA, aHb + 3 * TA, offA, offB, wm, wn, acc);
        __syncthreads();
    }

    float* Cb = &g_QG[b][0][0];
    const int mB = mt * 128 + wm * 32 + (lane >> 2);
    const int nB = nt * 128 + wn * 32 + 2 * (lane & 3);
#pragma unroll
    for (int mf = 0; mf < 2; mf++) {
        int r = mB + mf * 16;
#pragma unroll
        for (int nb = 0; nb < 4; nb++) {
            int cc = nB + nb * 8;
            float2 v0; v0.x = acc[mf][nb][0]; v0.y = acc[mf][nb][1];
            float2 v1; v1.x = acc[mf][nb][2]; v1.y = acc[mf][nb][3];
            *(float2*)&Cb[(size_t)r * NC + cc] = v0;
            *(float2*)&Cb[(size_t)(r + 8) * NC + cc] = v1;
        }
    }
}

// =============================================================================
// gemm_tc<1>: P = W_out*M (K=512), A=W_out split copy, B=M split via trans,
// pipelined. grid (2,2,NB). Output Phi/Plo split bf16.
// =============================================================================
__global__ __launch_bounds__(NT) void gemm_tc1() {
    extern __shared__ __align__(16) char sm[];
    const u32 smb = smem_u32(sm);
    const int nt = blockIdx.x, mt = blockIdx.y, b = blockIdx.z;
    const int tid = threadIdx.x, lane = tid & 31, wid = tid >> 5;
    const int wm = wid >> 2, wn = wid & 3;
    const int g = lane >> 3, r8 = lane & 7;
    const int offA = (r8 + (g & 1) * 8) * LDW + (g >> 1) * 8;
    const int offBT = (r8 + (g & 1) * 8) * LDWB + (g >> 1) * 8;
    const int fr = tid >> 2, fs = (tid & 3) * 32;
    const int r2 = tid >> 3, f2 = (tid & 7) * 32;

    float acc[2][4][4] = {};
    const int NCH = 8;

#define TC1_FILL(st, c) do {                                                        \
    const int _k0 = (c) * 64;                                                       \
    const u32 _sb = smb + (st) * STG_T;                                             \
    const char* _ah = (const char*)(g_Wouthi + (size_t)(mt * 128 + fr) * NH + _k0) + fs; \
    const char* _al = (const char*)(g_Woutlo + (size_t)(mt * 128 + fr) * NH + _k0) + fs; \
    u32 _dA = _sb + fr * 144 + fs;                                                  \
    CP16(_dA, _ah); CP16(_dA + 16, _ah + 16);                                       \
    CP16(_dA + TA, _al); CP16(_dA + TA + 16, _al + 16);                             \
    const char* _bh = (const char*)&g_Mhi[b][_k0 + r2][nt * 128] + f2;              \
    const char* _bl = (const char*)&g_Mlo[b][_k0 + r2][nt * 128] + f2;              \
    u32 _dB = _sb + 2 * TA + r2 * 272 + f2;                                         \
    CP16(_dB, _bh); CP16(_dB + 16, _bh + 16);                                       \
    CP16(_dB + TTB, _bl); CP16(_dB + TTB + 16, _bl + 16);                           \
    CP_COMMIT();                                                                    \
} while (0)

    TC1_FILL(0, 0);
    for (int c = 0; c < NCH; c++) {
        const int st = c & 1;
        if (c + 1 < NCH) { TC1_FILL(st ^ 1, c + 1); CP_WAIT1(); }
        else CP_WAIT0();
        __syncthreads();
        const u32 aHb = smb + st * STG_T;
        mma_stage<true>(aHb, aHb + TA, aHb + 2 * TA, aHb + 2 * TA + TTB, offA, offBT, wm, wn, acc);
        __syncthreads();
    }

    const int mB = mt * 128 + wm * 32 + (lane >> 2);
    const int nB = nt * 128 + wn * 32 + 2 * (lane & 3);
#pragma unroll
    for (int mf = 0; mf < 2; mf++) {
        int r = mB + mf * 16;
#pragma unroll
        for (int nb = 0; nb < 4; nb++) {
            int cc = nB + nb * 8;
            u32 hw, lw;
            split2_u32(acc[mf][nb][0], acc[mf][nb][1], hw, lw);
            *(u32*)&g_Phi[b][r][cc] = hw;
            *(u32*)&g_Plo[b][r][cc] = lw;
            split2_u32(acc[mf][nb][2], acc[mf][nb][3], hw, lw);
            *(u32*)&g_Phi[b][r + 8][cc] = hw;
            *(u32*)&g_Plo[b][r + 8][cc] = lw;
        }
    }
}

// =============================================================================
// attn: sim -> softmax -> M = attn*Wv; writes M split bf16. grid (8,NB), 256t.
// =============================================================================
__global__ __launch_bounds__(256) void attn_kernel(const float* __restrict__ wqkv) {
    const int h = blockIdx.x, b = blockIdx.y;
    __shared__ float S[64][65];
    __shared__ __align__(16) float Buf[4160];
    const int tid = threadIdx.x, tx = tid & 15, ty = tid >> 4;

    const float* QGb = &g_QG[b][h * 64][0];
    const float* Wk = wqkv + (size_t)(NH + h * 64) * NC;
    const float* Wv = wqkv + (size_t)(2 * NH + h * 64) * NC;
    float* Qs = Buf;
    float* Ks = Buf + 64 * 32;

    float acc[4][4] = {};
    for (int kc = 0; kc < NC; kc += 32) {
#pragma unroll
        for (int it = 0; it < 2; it++) {
            int idx = it * 256 + tid;
            int row = idx >> 3, c4 = idx & 7;
            *(float4*)&Qs[row * 32 + c4 * 4] = *(const float4*)(QGb + (size_t)row * NC + kc + c4 * 4);
            float4 v = *(const float4*)(Wk + (size_t)row * NC + kc + c4 * 4);
            Ks[(c4 * 4 + 0) * 65 + row] = v.x;
            Ks[(c4 * 4 + 1) * 65 + row] = v.y;
            Ks[(c4 * 4 + 2) * 65 + row] = v.z;
            Ks[(c4 * 4 + 3) * 65 + row] = v.w;
        }
        __syncthreads();
#pragma unroll
        for (int kk = 0; kk < 32; kk++) {
            float a[4], bb[4];
#pragma unroll
            for (int i = 0; i < 4; i++) a[i] = Qs[(ty + 16 * i) * 32 + kk];
#pragma unroll
            for (int j = 0; j < 4; j++) bb[j] = Ks[kk * 65 + tx + 16 * j];
#pragma unroll
            for (int i = 0; i < 4; i++)
#pragma unroll
                for (int j = 0; j < 4; j++) acc[i][j] += a[i] * bb[j];
        }
        __syncthreads();
    }
    const float scale = 0.125f;
#pragma unroll
    for (int i = 0; i < 4; i++)
#pragma unroll
        for (int j = 0; j < 4; j++)
            S[ty + 16 * i][tx + 16 * j] = acc[i][j] * scale;
    __syncthreads();

    if (tid < 64) {
        float m = -1e30f;
        for (int j = 0; j < 64; j++) m = fmaxf(m, S[tid][j]);
        float sum = 0.f;
        for (int j = 0; j < 64; j++) {
            float e = expf(S[tid][j] - m);
            S[tid][j] = e; sum += e;
        }
        float inv = 1.f / sum;
        for (int j = 0; j < 64; j++) S[tid][j] *= inv;
    }
    __syncthreads();

    float* Vs = Buf;
    for (int cc = 0; cc < NC; cc += 64) {
#pragma unroll
        for (int it = 0; it < 4; it++) {
            int idx = it * 256 + tid;
            int row = idx >> 4, c4 = idx & 15;
            *(float4*)&Vs[row * 64 + c4 * 4] = *(const float4*)(Wv + (size_t)row * NC + cc + c4 * 4);
        }
        __syncthreads();
        float o[4][4] = {};
        for (int j = 0; j < 64; j++) {
            float a[4], vv[4];
#pragma unroll
            for (int i = 0; i < 4; i++) a[i] = S[ty + 16 * i][j];
#pragma unroll
            for (int jj = 0; jj < 4; jj++) vv[jj] = Vs[j * 64 + tx + 16 * jj];
#pragma unroll
            for (int i = 0; i < 4; i++)
#pragma unroll
                for (int jj = 0; jj < 4; jj++) o[i][jj] += a[i] * vv[jj];
        }
#pragma unroll
        for (int i = 0; i < 4; i++)
#pragma unroll
            for (int jj = 0; jj < 4; jj++) {
                __nv_bfloat16 hv, lv;
                split1(o[i][jj], hv, lv);
                int hd = h * 64 + ty + 16 * i, ccol = cc + tx + 16 * jj;
                g_Mhi[b][hd][ccol] = hv;
                g_Mlo[b][hd][ccol] = lv;
            }
        __syncthreads();
    }
}

// =============================================================================
// final_mma: out = P*X + bias. A = Phi/Plo copy, B = Xhi/Xlo via trans.
// grid (32,2,NB), 512 threads, pipelined.
// =============================================================================
__global__ __launch_bounds__(NT) void final_mma(const float* __restrict__ bias,
                                                float* __restrict__ out) {
    extern __shared__ __align__(16) char sm[];
    const u32 smb = smem_u32(sm);
    const int nt = blockIdx.x, mt = blockIdx.y, b = blockIdx.z;
    const int tid = threadIdx.x, lane = tid & 31, wid = tid >> 5;
    const int wm = wid >> 2, wn = wid & 3;
    const int g = lane >> 3, r8 = lane & 7;
    const int offA = (r8 + (g & 1) * 8) * LDW + (g >> 1) * 8;
    const int offBT = (r8 + (g & 1) * 8) * LDWB + (g >> 1) * 8;
    const int fr = tid >> 2, fs = (tid & 3) * 32;
    const int r2 = tid >> 3, f2 = (tid & 7) * 32;

    float acc[2][4][4] = {};
    const int NCH = 4;

#define FIN_FILL(st, c) do {                                                        \
    const int _k0 = (c) * 64;                                                       \
    const u32 _sb = smb + (st) * STG_T;                                             \
    const char* _ah = (const char*)&g_Phi[b][mt * 128 + fr][_k0] + fs;              \
    const char* _al = (const char*)&g_Plo[b][mt * 128 + fr][_k0] + fs;              \
    u32 _dA = _sb + fr * 144 + fs;                                                  \
    CP16(_dA, _ah); CP16(_dA + 16, _ah + 16);                                       \
    CP16(_dA + TA, _al); CP16(_dA + TA + 16, _al + 16);                             \
    const char* _bh = (const char*)&g_Xhi[b][_k0 + r2][nt * 128] + f2;              \
    const char* _bl = (const char*)&g_Xlo[b][_k0 + r2][nt * 128] + f2;              \
    u32 _dB = _sb + 2 * TA + r2 * 272 + f2;                                         \
    CP16(_dB, _bh); CP16(_dB + 16, _bh + 16);                                       \
    CP16(_dB + TTB, _bl); CP16(_dB + TTB + 16, _bl + 16);                           \
    CP_COMMIT();                                                                    \
} while (0)

    FIN_FILL(0, 0);
    for (int c = 0; c < NCH; c++) {
        const int st = c & 1;
        if (c + 1 < NCH) { FIN_FILL(st ^ 1, c + 1); CP_WAIT1(); }
        else CP_WAIT0();
        __syncthreads();
        const u32 aHb = smb + st * STG_T;
        mma_stage<true>(aHb, aHb + TA, aHb + 2 * TA, aHb + 2 * TA + TTB, offA, offBT, wm, wn, acc);
        __syncthreads();
    }

    const int coB = mt * 128 + wm * 32 + (lane >> 2);
    const int nsB = nt * 128 + wn * 32 + 2 * (lane & 3);
#pragma unroll
    for (int mf = 0; mf < 2; mf++) {
        int co = coB + mf * 16;
        float bv0 = bias[co], bv1 = bias[co + 8];
        float* row0 = out + ((size_t)b * NC + co) * NS;
        float* row1 = out + ((size_t)b * NC + co + 8) * NS;
#pragma unroll
        for (int nb = 0; nb < 4; nb++) {
            int cc = nsB + nb * 8;
            float2 v0; v0.x = acc[mf][nb][0] + bv0; v0.y = acc[mf][nb][1] + bv0;
            float2 v1; v1.x = acc[mf][nb][2] + bv1; v1.y = acc[mf][nb][3] + bv1;
            *(float2*)&row0[cc] = v0;
            *(float2*)&row1[cc] = v1;
        }
    }
}

// =============================================================================
extern "C" void kernel_launch(void* const* d_in, const int* in_sizes, int n_in,
                              void* d_out, int out_size) {
    (void)in_sizes; (void)n_in; (void)out_size;
    const float* x     = (const float*)d_in[0];
    const float* w_qkv = (const float*)d_in[1];
    const float* w_out = (const float*)d_in[2];
    const float* b_out = (const float*)d_in[3];
    float* out = (float*)d_out;

    cudaFuncSetAttribute(gram_mma, cudaFuncAttributeMaxDynamicSharedMemorySize, PIPE_A);
    cudaFuncSetAttribute(gemm_tc0, cudaFuncAttributeMaxDynamicSharedMemorySize, PIPE_A);
    cudaFuncSetAttribute(gemm_tc1, cudaFuncAttributeMaxDynamicSharedMemorySize, PIPE_T);
    cudaFuncSetAttribute(final_mma, cudaFuncAttributeMaxDynamicSharedMemorySize, PIPE_T);

    convert_x<<<NB * NC * NS / (256 * 8), 256>>>(x);
    convert_w<<<(NH * NC + NC * NH) / (256 * 8), 256>>>(w_qkv, w_out);
    gram_mma<<<dim3(3, 2, NB), NT, PIPE_A>>>();
    reduce_split_g<<<dim3(16, NB), 256>>>();
    gemm_tc0<<<dim3(2, 4, NB), NT, PIPE_A>>>();
    attn_kernel<<<dim3(NHEADS, NB), 256>>>(w_qkv);
    gemm_tc1<<<dim3(2, 2, NB), NT, PIPE_T>>>();
    final_mma<<<dim3(32, 2, NB), NT, PIPE_T>>>(b_out, out);
}